// round 13
// baseline (speedup 1.0000x reference)
#include <cuda_runtime.h>
#include <cuda_bf16.h>
#include <math.h>

#define BB     2
#define CC     256
#define NQ     4096
#define HEADS  4
#define DH     64
#define KK     64
#define GROUPS 32
#define CPG    8
#define EPS    1e-6f

#define PADK   40       // bf16 elems per k=32 smem row (80B): conflict-free frags
#define NTILES (NQ/32)  // 128 n-tiles for gn partials

// Scratch (device globals; no allocation allowed)
__device__ __nv_bfloat16 g_xt [BB*NQ*CC];   // x^T bf16, [b][n][c]
__device__ __nv_bfloat16 g_qb [BB*NQ*CC];   // Q bf16, [b][n][c]  c = head*64 + d
__device__ __nv_bfloat16 g_kb [BB*NQ*CC];   // K bf16, [b][n][c]
__device__ __nv_bfloat16 g_vb [BB*NQ*CC];   // V bf16, [b][n][c]
__device__ __nv_bfloat16 g_atb[BB*NQ*CC];   // attn out bf16, [b][n][c] c=d*HEADS+h
__device__ float         g_ps [BB*GROUPS*NTILES];   // gn partial sums
__device__ float         g_ps2[BB*GROUPS*NTILES];   // gn partial sumsq
__device__ float         g_mean[BB][GROUPS];
__device__ float         g_rstd[BB][GROUPS];
__device__ __nv_bfloat16 g_wpb[BB*3*CC*CC]; // GN-folded qkv weights bf16
__device__ __nv_bfloat16 g_wob[CC*CC];      // Wo bf16 [o][c]
__device__ float         g_bp [BB*3*CC];    // GN-folded biases fp32

// ---------------------------------------------------------------------------
// helpers
// ---------------------------------------------------------------------------
__device__ __forceinline__ void mma_bf16(float d[4], const unsigned a[4],
                                         const unsigned b[2]) {
    asm("mma.sync.aligned.m16n8k16.row.col.f32.bf16.bf16.f32 "
        "{%0,%1,%2,%3}, {%4,%5,%6,%7}, {%8,%9}, {%0,%1,%2,%3};"
        : "+f"(d[0]), "+f"(d[1]), "+f"(d[2]), "+f"(d[3])
        : "r"(a[0]), "r"(a[1]), "r"(a[2]), "r"(a[3]),
          "r"(b[0]), "r"(b[1]));
}

__device__ __forceinline__ void cp16(unsigned dst, const void* src) {
    asm volatile("cp.async.cg.shared.global [%0], [%1], 16;"
                 :: "r"(dst), "l"(src));
}
#define CP_COMMIT() asm volatile("cp.async.commit_group;")
#define CP_WAIT(n)  asm volatile("cp.async.wait_group %0;" :: "n"(n))

// packed f32x2 helpers (sm_103a dual-f32 pipe)
__device__ __forceinline__ unsigned long long pk2(unsigned lo, unsigned hi) {
    unsigned long long r;
    asm("mov.b64 %0, {%1,%2};" : "=l"(r) : "r"(lo), "r"(hi));
    return r;
}
__device__ __forceinline__ void upk2(unsigned long long v, float& lo, float& hi) {
    unsigned a, b;
    asm("mov.b64 {%0,%1}, %2;" : "=r"(a), "=r"(b) : "l"(v));
    lo = __uint_as_float(a); hi = __uint_as_float(b);
}
__device__ __forceinline__ unsigned long long bfx2(unsigned u) {
    return pk2(u << 16, u & 0xFFFF0000u);   // bf16x2 -> packed f32x2
}
__device__ __forceinline__ void ffma2(unsigned long long& d,
                                      unsigned long long a,
                                      unsigned long long b) {
    asm("fma.rn.f32x2 %0, %1, %2, %0;" : "+l"(d) : "l"(a), "l"(b));
}

// ---------------------------------------------------------------------------
// Fused transpose + GN partial stats (round-12)
// ---------------------------------------------------------------------------
__global__ void xpose_gn(const float* __restrict__ x)
{
    __shared__ float t[32][33];
    __shared__ float red[8][4][2];
    const int b = blockIdx.z;
    const int n0 = blockIdx.x * 32, c0 = blockIdx.y * 32;
    const float* xp = x + (size_t)b * CC * NQ;
    const int tx = threadIdx.x, ty = threadIdx.y;

    float vs[4];
    #pragma unroll
    for (int k = 0; k < 4; k++) {
        int cl = k * 8 + ty;
        float v = xp[(size_t)(c0 + cl) * NQ + n0 + tx];
        t[cl][tx] = v;
        vs[k] = v;
    }
    #pragma unroll
    for (int k = 0; k < 4; k++) {
        float s = vs[k], s2 = vs[k] * vs[k];
        #pragma unroll
        for (int o = 16; o; o >>= 1) {
            s  += __shfl_xor_sync(~0u, s,  o);
            s2 += __shfl_xor_sync(~0u, s2, o);
        }
        if (tx == 0) { red[ty][k][0] = s; red[ty][k][1] = s2; }
    }
    __syncthreads();

    __nv_bfloat16* o = g_xt + (size_t)b * NQ * CC;
    #pragma unroll
    for (int k = 0; k < 4; k++) {
        int nl = k * 8 + ty;
        o[(size_t)(n0 + nl) * CC + c0 + tx] = __float2bfloat16_rn(t[tx][nl]);
    }

    if (ty == 0 && tx < 4) {
        float s = 0.f, s2 = 0.f;
        #pragma unroll
        for (int y = 0; y < 8; y++) { s += red[y][tx][0]; s2 += red[y][tx][1]; }
        int grp = blockIdx.y * 4 + tx;
        g_ps [(b * GROUPS + grp) * NTILES + blockIdx.x] = s;
        g_ps2[(b * GROUPS + grp) * NTILES + blockIdx.x] = s2;
    }
}

// ---------------------------------------------------------------------------
// GN finish (round-12)
// ---------------------------------------------------------------------------
__global__ void gn_finish()
{
    const int g = blockIdx.x, b = blockIdx.y;
    const int tid = threadIdx.x;
    float s  = g_ps [(b * GROUPS + g) * NTILES + tid];
    float s2 = g_ps2[(b * GROUPS + g) * NTILES + tid];
    #pragma unroll
    for (int o = 16; o; o >>= 1) {
        s  += __shfl_xor_sync(~0u, s,  o);
        s2 += __shfl_xor_sync(~0u, s2, o);
    }
    __shared__ float as[4], as2[4];
    int w = tid >> 5;
    if ((tid & 31) == 0) { as[w] = s; as2[w] = s2; }
    __syncthreads();
    if (tid == 0) {
        float ts = 0.f, ts2 = 0.f;
        #pragma unroll
        for (int i = 0; i < 4; i++) { ts += as[i]; ts2 += as2[i]; }
        const float NE = (float)(CPG * NQ);
        float m = ts / NE;
        float var = ts2 / NE - m * m;
        g_mean[b][g] = m;
        g_rstd[b][g] = rsqrtf(var + EPS);
    }
}

// ---------------------------------------------------------------------------
// Weight prep (round-12)
// ---------------------------------------------------------------------------
__global__ void wprep(const float* __restrict__ wq, const float* __restrict__ bq,
                      const float* __restrict__ wk, const float* __restrict__ bk,
                      const float* __restrict__ wv, const float* __restrict__ bv,
                      const float* __restrict__ wo,
                      const float* __restrict__ gsc, const float* __restrict__ gbi)
{
    const int which = blockIdx.x, b = blockIdx.y;
    const int obase = blockIdx.z * 32;
    const int tid = threadIdx.x;
    const int wid = tid >> 5, lane = tid & 31;

    if (which == 3) {
        #pragma unroll
        for (int oo = 0; oo < 4; oo++) {
            int o = obase + wid + oo * 8;
            #pragma unroll
            for (int cb = 0; cb < CC; cb += 32) {
                int c = cb + lane;
                g_wob[(size_t)o * CC + c] =
                    __float2bfloat16_rn(wo[(size_t)o * CC + c]);
            }
        }
        return;
    }

    const float* W    = which == 0 ? wq : which == 1 ? wk : wv;
    const float* bias = which == 0 ? bq : which == 1 ? bk : bv;

    __shared__ float coef[CC], sub[CC];
    {
        int c = tid;
        int g = c >> 3;
        float r = g_rstd[b][g], m = g_mean[b][g];
        float sc = gsc[c];
        coef[c] = sc * r;
        sub[c]  = gbi[c] - m * r * sc;
    }
    __syncthreads();

    __nv_bfloat16* Wp = g_wpb + (size_t)(b*3 + which) * CC * CC;
    float* bp = g_bp + (b*3 + which) * CC;

    #pragma unroll
    for (int oo = 0; oo < 4; oo++) {
        int o = obase + wid + oo * 8;
        float acc = 0.f;
        #pragma unroll
        for (int cb = 0; cb < CC; cb += 32) {
            int c = cb + lane;
            float w = W[(size_t)o * CC + c];
            Wp[(size_t)o * CC + c] = __float2bfloat16_rn(w * coef[c]);
            acc += w * sub[c];
        }
        #pragma unroll
        for (int off = 16; off; off >>= 1)
            acc += __shfl_xor_sync(~0u, acc, off);
        if (lane == 0) bp[o] = bias[o] + acc;
    }
}

// ---------------------------------------------------------------------------
// Fused QKV GEMM v3: tile 64(n=M) x 128(o=N), 256 thr, warp 32x32, 3 CTAs/SM.
// O[b][n][o] = sum_c x^T[n][c] * W'[o][c] + bias'[o]
// grid (NQ/64, 6, B) = 768 CTAs. 4-stage cp.async, one sync per k-step.
// ---------------------------------------------------------------------------
#define QKV_SMEM (4 * (64 + 128) * PADK * 2)

__global__ void __launch_bounds__(256, 3)
gemm_qkv()
{
    extern __shared__ __nv_bfloat16 smem_bf[];
    __nv_bfloat16* As = smem_bf;                    // [4][64][PADK]  x^T
    __nv_bfloat16* Bs = smem_bf + 4*64*PADK;        // [4][128][PADK] W'
    const unsigned* As32 = (const unsigned*)As;
    const unsigned* Bs32 = (const unsigned*)Bs;

    const int nb    = blockIdx.x * 64;
    const int which = blockIdx.y >> 1;
    const int ob    = (blockIdx.y & 1) * 128;
    const int b     = blockIdx.z;

    const __nv_bfloat16* Xt = g_xt  + (size_t)b * NQ * CC;
    const __nv_bfloat16* W  = g_wpb + (size_t)(b*3 + which) * CC * CC;
    const float* bias = g_bp + (b*3 + which) * CC;

    const int tid  = threadIdx.x;
    const int wid  = tid >> 5, lane = tid & 31;
    const int wm   = wid & 1,  wn   = wid >> 1;   // 2 m-warps x 4 n-warps
    const int g    = lane >> 2, t   = lane & 3;

    const unsigned as_base = (unsigned)__cvta_generic_to_shared(As);
    const unsigned bs_base = (unsigned)__cvta_generic_to_shared(Bs);

    const int cp_r = tid >> 2, cp_s = tid & 3;   // 64 rows x 4 chunks

    #define LOAD_STAGE(s, c0)                                                  \
    {                                                                          \
        cp16(as_base + (((s)*64 + cp_r) * PADK + cp_s * 8) * 2,                \
             Xt + (size_t)(nb + cp_r) * CC + (c0) + cp_s * 8);                 \
        _Pragma("unroll")                                                      \
        for (int j = 0; j < 2; j++) {                                          \
            int row = cp_r + j * 64;                                           \
            cp16(bs_base + (((s)*128 + row) * PADK + cp_s * 8) * 2,            \
                 W + (size_t)(ob + row) * CC + (c0) + cp_s * 8);               \
        }                                                                      \
        CP_COMMIT();                                                           \
    }

    float acc[2][4][4];
    #pragma unroll
    for (int i = 0; i < 2; i++)
        #pragma unroll
        for (int j = 0; j < 4; j++)
            #pragma unroll
            for (int r = 0; r < 4; r++) acc[i][j][r] = 0.f;

    LOAD_STAGE(0, 0);
    LOAD_STAGE(1, 32);
    LOAD_STAGE(2, 64);

    #pragma unroll
    for (int ks = 0; ks < 8; ks++) {
        const int cur = ks & 3;
        if (ks < 6)      { CP_WAIT(2); }
        else if (ks == 6){ CP_WAIT(1); }
        else             { CP_WAIT(0); }
        __syncthreads();
        if (ks < 5) LOAD_STAGE((ks + 3) & 3, (ks + 3) * 32);

        #pragma unroll
        for (int kk = 0; kk < 2; kk++) {
            unsigned afr[2][4], bfr[4][2];
            #pragma unroll
            for (int mt = 0; mt < 2; mt++) {
                int base = (cur*64 + wm*32 + mt*16 + g) * (PADK/2) + kk*8 + t;
                afr[mt][0] = As32[base];
                afr[mt][1] = As32[base + 8*(PADK/2)];
                afr[mt][2] = As32[base + 4];
                afr[mt][3] = As32[base + 8*(PADK/2) + 4];
            }
            #pragma unroll
            for (int nt = 0; nt < 4; nt++) {
                int base = (cur*128 + wn*32 + nt*8 + g) * (PADK/2) + kk*8 + t;
                bfr[nt][0] = Bs32[base];
                bfr[nt][1] = Bs32[base + 4];
            }
            #pragma unroll
            for (int mt = 0; mt < 2; mt++)
                #pragma unroll
                for (int nt = 0; nt < 4; nt++)
                    mma_bf16(acc[mt][nt], afr[mt], bfr[nt]);
        }
    }
    #undef LOAD_STAGE

    __nv_bfloat16* O = (which == 0 ? g_qb : which == 1 ? g_kb : g_vb)
                       + (size_t)b * NQ * CC;
    #pragma unroll
    for (int nt = 0; nt < 4; nt++) {
        int o = ob + wn*32 + nt*8 + 2*t;
        float bb0 = bias[o], bb1 = bias[o + 1];
        #pragma unroll
        for (int mt = 0; mt < 2; mt++) {
            int n0 = nb + wm*32 + mt*16 + g;
            __nv_bfloat162 v0 = {__float2bfloat16_rn(acc[mt][nt][0] + bb0),
                                 __float2bfloat16_rn(acc[mt][nt][1] + bb1)};
            __nv_bfloat162 v1 = {__float2bfloat16_rn(acc[mt][nt][2] + bb0),
                                 __float2bfloat16_rn(acc[mt][nt][3] + bb1)};
            *(__nv_bfloat162*)&O[(size_t)n0 * CC + o]       = v0;
            *(__nv_bfloat162*)&O[(size_t)(n0 + 8) * CC + o] = v1;
        }
    }
}

// ---------------------------------------------------------------------------
// Sparse attention (round-11/12, unchanged)
// ---------------------------------------------------------------------------
__global__ void __launch_bounds__(128)
attn_kernel(const int* __restrict__ mask, const int* __restrict__ aidx)
{
    __shared__ int   sidx[4][64];
    __shared__ float sl  [4][64][4];

    const int wrp = threadIdx.x >> 5, l = threadIdx.x & 31;
    const int gw = blockIdx.x * 4 + wrp;
    const int n  = gw & (NQ - 1);
    const int b  = gw >> 12;

    const __nv_bfloat16* qp = g_qb + ((size_t)b * NQ + n) * CC;
    const __nv_bfloat16* Kb = g_kb + (size_t)b * NQ * CC;
    const __nv_bfloat16* Vb = g_vb + (size_t)b * NQ * CC;

    unsigned long long q2[4];
    {
        uint4 qw = *(const uint4*)(qp + 8 * l);
        q2[0] = bfx2(qw.x); q2[1] = bfx2(qw.y);
        q2[2] = bfx2(qw.z); q2[3] = bfx2(qw.w);
    }

    int nact;
    {
        int i0 = aidx[n * KK + l];
        int i1 = aidx[n * KK + l + 32];
        int m0 = mask[n * KK + l];
        int m1 = mask[n * KK + l + 32];
        unsigned bl0 = __ballot_sync(~0u, m0 != 0);
        unsigned bl1 = __ballot_sync(~0u, m1 != 0);
        int cnt0 = __popc(bl0);
        nact = cnt0 + __popc(bl1);
        unsigned below = (1u << l) - 1u;
        if (m0) sidx[wrp][__popc(bl0 & below)]        = i0;
        if (m1) sidx[wrp][cnt0 + __popc(bl1 & below)] = i1;
    }
    __syncwarp();

    const int h = l >> 3, i = l & 7;

    #pragma unroll 4
    for (int key = 0; key < nact; key++) {
        const int idx = sidx[wrp][key];
        uint4 kw = ((const uint4*)(Kb + (size_t)idx * CC))[l];
        unsigned long long a2 = 0ull;
        ffma2(a2, q2[0], bfx2(kw.x));
        ffma2(a2, q2[1], bfx2(kw.y));
        ffma2(a2, q2[2], bfx2(kw.z));
        ffma2(a2, q2[3], bfx2(kw.w));
        float plo, phi; upk2(a2, plo, phi);
        float p = plo + phi;
        p += __shfl_xor_sync(~0u, p, 4);
        p += __shfl_xor_sync(~0u, p, 2);
        p += __shfl_xor_sync(~0u, p, 1);
        if (i == (key & 7)) sl[wrp][key][h] = p;
    }
    __syncwarp();

    float lg[8];
    #pragma unroll
    for (int j = 0; j < 8; j++) {
        int key = i + 8 * j;
        lg[j] = (key < nact) ? sl[wrp][key][h] : -INFINITY;
    }
    float mx = lg[0];
    #pragma unroll
    for (int j = 1; j < 8; j++) mx = fmaxf(mx, lg[j]);
    mx = fmaxf(mx, __shfl_xor_sync(~0u, mx, 4));
    mx = fmaxf(mx, __shfl_xor_sync(~0u, mx, 2));
    mx = fmaxf(mx, __shfl_xor_sync(~0u, mx, 1));

    float e[8], s = 0.f;
    #pragma unroll
    for (int j = 0; j < 8; j++) { e[j] = __expf(lg[j] - mx); s += e[j]; }
    s += __shfl_xor_sync(~0u, s, 4);
    s += __shfl_xor_sync(~0u, s, 2);
    s += __shfl_xor_sync(~0u, s, 1);
    const float inv = 1.f / s;

    #pragma unroll
    for (int j = 0; j < 8; j++)
        sl[wrp][i + 8 * j][h] = e[j] * inv;
    __syncwarp();

    unsigned long long vacc[4] = {0ull, 0ull, 0ull, 0ull};

    #pragma unroll 4
    for (int key = 0; key < nact; key++) {
        const int idx = sidx[wrp][key];
        const float wv = sl[wrp][key][h];
        unsigned wu = __float_as_uint(wv);
        unsigned long long w2 = pk2(wu, wu);
        uint4 vw = ((const uint4*)(Vb + (size_t)idx * CC))[l];
        ffma2(vacc[0], w2, bfx2(vw.x));
        ffma2(vacc[1], w2, bfx2(vw.y));
        ffma2(vacc[2], w2, bfx2(vw.z));
        ffma2(vacc[3], w2, bfx2(vw.w));
    }

    float acc[8];
    upk2(vacc[0], acc[0], acc[1]);
    upk2(vacc[1], acc[2], acc[3]);
    upk2(vacc[2], acc[4], acc[5]);
    upk2(vacc[3], acc[6], acc[7]);

    __nv_bfloat16* at = g_atb + ((size_t)b * NQ + n) * CC;
    #pragma unroll
    for (int j = 0; j < 8; j++) {
        int c = 8 * l + j;                   // c = 64*h + d
        at[(c & 63) * HEADS + h] = __float2bfloat16_rn(acc[j]);
    }
}

// ---------------------------------------------------------------------------
// Output projection + residual v3: tile 128(o=M) x 64(n=N), warp 32x32,
// 3 CTAs/SM. grid (NQ/64, CC/128, B) = 256 CTAs.
// ---------------------------------------------------------------------------
#define OUT_SMEM (4 * (128 + 64) * PADK * 2)

__global__ void __launch_bounds__(256, 3)
gemm_out(const float* __restrict__ bo,
         const float* __restrict__ x,  float* __restrict__ out)
{
    extern __shared__ __nv_bfloat16 smem_bf[];
    __nv_bfloat16* As = smem_bf;                    // [4][128][PADK] Wo
    __nv_bfloat16* Bs = smem_bf + 4*128*PADK;       // [4][64][PADK]  at
    const unsigned* As32 = (const unsigned*)As;
    const unsigned* Bs32 = (const unsigned*)Bs;

    const int nb = blockIdx.x * 64, ob = blockIdx.y * 128, b = blockIdx.z;
    const __nv_bfloat16* A = g_atb + (size_t)b * NQ * CC;

    const int tid  = threadIdx.x;
    const int wid  = tid >> 5, lane = tid & 31;
    const int wm   = wid & 3,  wn   = wid >> 2;   // 4 m-warps x 2 n-warps
    const int g    = lane >> 2, t   = lane & 3;

    const unsigned as_base = (unsigned)__cvta_generic_to_shared(As);
    const unsigned bs_base = (unsigned)__cvta_generic_to_shared(Bs);

    const int cp_r = tid >> 2, cp_s = tid & 3;

    #define LOAD_STAGE(s, c0)                                                  \
    {                                                                          \
        _Pragma("unroll")                                                      \
        for (int j = 0; j < 2; j++) {                                          \
            int row = cp_r + j * 64;                                           \
            cp16(as_base + (((s)*128 + row) * PADK + cp_s * 8) * 2,            \
                 g_wob + (size_t)(ob + row) * CC + (c0) + cp_s * 8);           \
        }                                                                      \
        cp16(bs_base + (((s)*64 + cp_r) * PADK + cp_s * 8) * 2,                \
             A + (size_t)(nb + cp_r) * CC + (c0) + cp_s * 8);                  \
        CP_COMMIT();                                                           \
    }

    float acc[2][4][4];
    #pragma unroll
    for (int i = 0; i < 2; i++)
        #pragma unroll
        for (int j = 0; j < 4; j++)
            #pragma unroll
            for (int r = 0; r < 4; r++) acc[i][j][r] = 0.f;

    LOAD_STAGE(0, 0);
    LOAD_STAGE(1, 32);
    LOAD_STAGE(2, 64);

    #pragma unroll
    for (int ks = 0; ks < 8; ks++) {
        const int cur = ks & 3;
        if (ks < 6)      { CP_WAIT(2); }
        else if (ks == 6){ CP_WAIT(1); }
        else             { CP_WAIT(0); }
        __syncthreads();
        if (ks < 5) LOAD_STAGE((ks + 3) & 3, (ks + 3) * 32);

        #pragma unroll
        for (int kk = 0; kk < 2; kk++) {
            unsigned afr[2][4], bfr[4][2];
            #pragma unroll
            for (int mt = 0; mt < 2; mt++) {
                int base = (cur*128 + wm*32 + mt*16 + g) * (PADK/2) + kk*8 + t;
                afr[mt][0] = As32[base];
                afr[mt][1] = As32[base + 8*(PADK/2)];
                afr[mt][2] = As32[base + 4];
                afr[mt][3] = As32[base + 8*(PADK/2) + 4];
            }
            #pragma unroll
            for (int nt = 0; nt < 4; nt++) {
                int base = (cur*64 + wn*32 + nt*8 + g) * (PADK/2) + kk*8 + t;
                bfr[nt][0] = Bs32[base];
                bfr[nt][1] = Bs32[base + 4];
            }
            #pragma unroll
            for (int mt = 0; mt < 2; mt++)
                #pragma unroll
                for (int nt = 0; nt < 4; nt++)
                    mma_bf16(acc[mt][nt], afr[mt], bfr[nt]);
        }
    }
    #undef LOAD_STAGE

    const float* xp = x   + (size_t)b * CC * NQ;
    float*       op = out + (size_t)b * CC * NQ;
    #pragma unroll
    for (int mt = 0; mt < 2; mt++) {
        int o0 = ob + wm*32 + mt*16 + g;
        float bb0 = bo[o0], bb1 = bo[o0 + 8];
        #pragma unroll
        for (int nt = 0; nt < 4; nt++) {
            int n = nb + wn*32 + nt*8 + 2*t;
            size_t base0 = (size_t)o0 * NQ + n;
            size_t base1 = (size_t)(o0 + 8) * NQ + n;
            float2 x0 = *(const float2*)&xp[base0];
            float2 x1 = *(const float2*)&xp[base1];
            float2 v0 = {acc[mt][nt][0] + bb0 + x0.x, acc[mt][nt][1] + bb0 + x0.y};
            float2 v1 = {acc[mt][nt][2] + bb1 + x1.x, acc[mt][nt][3] + bb1 + x1.y};
            *(float2*)&op[base0] = v0;
            *(float2*)&op[base1] = v1;
        }
    }
}

// ---------------------------------------------------------------------------
extern "C" void kernel_launch(void* const* d_in, const int* in_sizes, int n_in,
                              void* d_out, int out_size)
{
    const float* x    = (const float*)d_in[0];
    const int*   mask = (const int*)  d_in[1];
    const int*   aidx = (const int*)  d_in[2];
    const float* gsc  = (const float*)d_in[3];
    const float* gbi  = (const float*)d_in[4];
    const float* wq   = (const float*)d_in[5];
    const float* bq   = (const float*)d_in[6];
    const float* wk   = (const float*)d_in[7];
    const float* bk   = (const float*)d_in[8];
    const float* wv   = (const float*)d_in[9];
    const float* bv   = (const float*)d_in[10];
    const float* wo   = (const float*)d_in[11];
    const float* bo   = (const float*)d_in[12];
    float* out = (float*)d_out;

    cudaFuncSetAttribute(gemm_qkv, cudaFuncAttributeMaxDynamicSharedMemorySize,
                         QKV_SMEM);
    cudaFuncSetAttribute(gemm_out, cudaFuncAttributeMaxDynamicSharedMemorySize,
                         OUT_SMEM);

    xpose_gn<<<dim3(NQ / 32, CC / 32, BB), dim3(32, 8)>>>(x);

    gn_finish<<<dim3(GROUPS, BB), 128>>>();

    wprep<<<dim3(4, BB, 8), 256>>>(wq, bq, wk, bk, wv, bv, wo, gsc, gbi);

    gemm_qkv<<<dim3(NQ / 64, 6, BB), 256, QKV_SMEM>>>();

    attn_kernel<<<BB * NQ / 4, 128>>>(mask, aidx);

    gemm_out<<<dim3(NQ / 64, CC / 128, BB), 256, OUT_SMEM>>>(bo, x, out);
}

// round 14
// speedup vs baseline: 1.0809x; 1.0809x over previous
#include <cuda_runtime.h>
#include <cuda_bf16.h>
#include <math.h>

#define BB     2
#define CC     256
#define NQ     4096
#define HEADS  4
#define DH     64
#define KK     64
#define GROUPS 32
#define CPG    8
#define EPS    1e-6f

#define PADK   40       // bf16 elems per k=32 smem row (80B): conflict-free frags
#define NTILES (NQ/32)  // 128 n-tiles for gn partials

// Scratch (device globals; no allocation allowed)
__device__ __nv_bfloat16 g_xt [BB*NQ*CC];   // x^T bf16, [b][n][c]
__device__ __nv_bfloat16 g_qb [BB*NQ*CC];   // Q bf16, [b][n][c]  c = head*64 + d
__device__ __nv_bfloat16 g_kb [BB*NQ*CC];   // K bf16, [b][n][c]
__device__ __nv_bfloat16 g_vb [BB*NQ*CC];   // V bf16, [b][n][c]
__device__ __nv_bfloat16 g_atb[BB*NQ*CC];   // attn out bf16, [b][n][c] c=d*HEADS+h
__device__ float         g_ps [BB*GROUPS*NTILES];   // gn partial sums
__device__ float         g_ps2[BB*GROUPS*NTILES];   // gn partial sumsq
__device__ float         g_mean[BB][GROUPS];
__device__ float         g_rstd[BB][GROUPS];
__device__ __nv_bfloat16 g_wpb[BB*3*CC*CC]; // GN-folded qkv weights bf16
__device__ __nv_bfloat16 g_wob[CC*CC];      // Wo bf16 [o][c]
__device__ float         g_bp [BB*3*CC];    // GN-folded biases fp32

// ---------------------------------------------------------------------------
// helpers
// ---------------------------------------------------------------------------
__device__ __forceinline__ void mma_bf16(float d[4], const unsigned a[4],
                                         const unsigned b[2]) {
    asm("mma.sync.aligned.m16n8k16.row.col.f32.bf16.bf16.f32 "
        "{%0,%1,%2,%3}, {%4,%5,%6,%7}, {%8,%9}, {%0,%1,%2,%3};"
        : "+f"(d[0]), "+f"(d[1]), "+f"(d[2]), "+f"(d[3])
        : "r"(a[0]), "r"(a[1]), "r"(a[2]), "r"(a[3]),
          "r"(b[0]), "r"(b[1]));
}

__device__ __forceinline__ void ldsm4(unsigned& r0, unsigned& r1,
                                      unsigned& r2, unsigned& r3,
                                      unsigned addr) {
    asm volatile("ldmatrix.sync.aligned.m8n8.x4.shared.b16 {%0,%1,%2,%3}, [%4];"
                 : "=r"(r0), "=r"(r1), "=r"(r2), "=r"(r3) : "r"(addr));
}

__device__ __forceinline__ void cp16(unsigned dst, const void* src) {
    asm volatile("cp.async.cg.shared.global [%0], [%1], 16;"
                 :: "r"(dst), "l"(src));
}
#define CP_COMMIT() asm volatile("cp.async.commit_group;")
#define CP_WAIT(n)  asm volatile("cp.async.wait_group %0;" :: "n"(n))

// packed f32x2 helpers (sm_103a dual-f32 pipe)
__device__ __forceinline__ unsigned long long pk2(unsigned lo, unsigned hi) {
    unsigned long long r;
    asm("mov.b64 %0, {%1,%2};" : "=l"(r) : "r"(lo), "r"(hi));
    return r;
}
__device__ __forceinline__ void upk2(unsigned long long v, float& lo, float& hi) {
    unsigned a, b;
    asm("mov.b64 {%0,%1}, %2;" : "=r"(a), "=r"(b) : "l"(v));
    lo = __uint_as_float(a); hi = __uint_as_float(b);
}
__device__ __forceinline__ unsigned long long bfx2(unsigned u) {
    return pk2(u << 16, u & 0xFFFF0000u);   // bf16x2 -> packed f32x2
}
__device__ __forceinline__ void ffma2(unsigned long long& d,
                                      unsigned long long a,
                                      unsigned long long b) {
    asm("fma.rn.f32x2 %0, %1, %2, %0;" : "+l"(d) : "l"(a), "l"(b));
}

// ---------------------------------------------------------------------------
// Fused transpose + GN partial stats
// ---------------------------------------------------------------------------
__global__ void xpose_gn(const float* __restrict__ x)
{
    __shared__ float t[32][33];
    __shared__ float red[8][4][2];
    const int b = blockIdx.z;
    const int n0 = blockIdx.x * 32, c0 = blockIdx.y * 32;
    const float* xp = x + (size_t)b * CC * NQ;
    const int tx = threadIdx.x, ty = threadIdx.y;

    float vs[4];
    #pragma unroll
    for (int k = 0; k < 4; k++) {
        int cl = k * 8 + ty;
        float v = xp[(size_t)(c0 + cl) * NQ + n0 + tx];
        t[cl][tx] = v;
        vs[k] = v;
    }
    #pragma unroll
    for (int k = 0; k < 4; k++) {
        float s = vs[k], s2 = vs[k] * vs[k];
        #pragma unroll
        for (int o = 16; o; o >>= 1) {
            s  += __shfl_xor_sync(~0u, s,  o);
            s2 += __shfl_xor_sync(~0u, s2, o);
        }
        if (tx == 0) { red[ty][k][0] = s; red[ty][k][1] = s2; }
    }
    __syncthreads();

    __nv_bfloat16* o = g_xt + (size_t)b * NQ * CC;
    #pragma unroll
    for (int k = 0; k < 4; k++) {
        int nl = k * 8 + ty;
        o[(size_t)(n0 + nl) * CC + c0 + tx] = __float2bfloat16_rn(t[tx][nl]);
    }

    if (ty == 0 && tx < 4) {
        float s = 0.f, s2 = 0.f;
        #pragma unroll
        for (int y = 0; y < 8; y++) { s += red[y][tx][0]; s2 += red[y][tx][1]; }
        int grp = blockIdx.y * 4 + tx;
        g_ps [(b * GROUPS + grp) * NTILES + blockIdx.x] = s;
        g_ps2[(b * GROUPS + grp) * NTILES + blockIdx.x] = s2;
    }
}

// ---------------------------------------------------------------------------
// GN finish
// ---------------------------------------------------------------------------
__global__ void gn_finish()
{
    const int g = blockIdx.x, b = blockIdx.y;
    const int tid = threadIdx.x;
    float s  = g_ps [(b * GROUPS + g) * NTILES + tid];
    float s2 = g_ps2[(b * GROUPS + g) * NTILES + tid];
    #pragma unroll
    for (int o = 16; o; o >>= 1) {
        s  += __shfl_xor_sync(~0u, s,  o);
        s2 += __shfl_xor_sync(~0u, s2, o);
    }
    __shared__ float as[4], as2[4];
    int w = tid >> 5;
    if ((tid & 31) == 0) { as[w] = s; as2[w] = s2; }
    __syncthreads();
    if (tid == 0) {
        float ts = 0.f, ts2 = 0.f;
        #pragma unroll
        for (int i = 0; i < 4; i++) { ts += as[i]; ts2 += as2[i]; }
        const float NE = (float)(CPG * NQ);
        float m = ts / NE;
        float var = ts2 / NE - m * m;
        g_mean[b][g] = m;
        g_rstd[b][g] = rsqrtf(var + EPS);
    }
}

// ---------------------------------------------------------------------------
// Weight prep: grid (4, B, 8), block 256
// ---------------------------------------------------------------------------
__global__ void wprep(const float* __restrict__ wq, const float* __restrict__ bq,
                      const float* __restrict__ wk, const float* __restrict__ bk,
                      const float* __restrict__ wv, const float* __restrict__ bv,
                      const float* __restrict__ wo,
                      const float* __restrict__ gsc, const float* __restrict__ gbi)
{
    const int which = blockIdx.x, b = blockIdx.y;
    const int obase = blockIdx.z * 32;
    const int tid = threadIdx.x;
    const int wid = tid >> 5, lane = tid & 31;

    if (which == 3) {
        #pragma unroll
        for (int oo = 0; oo < 4; oo++) {
            int o = obase + wid + oo * 8;
            #pragma unroll
            for (int cb = 0; cb < CC; cb += 32) {
                int c = cb + lane;
                g_wob[(size_t)o * CC + c] =
                    __float2bfloat16_rn(wo[(size_t)o * CC + c]);
            }
        }
        return;
    }

    const float* W    = which == 0 ? wq : which == 1 ? wk : wv;
    const float* bias = which == 0 ? bq : which == 1 ? bk : bv;

    __shared__ float coef[CC], sub[CC];
    {
        int c = tid;
        int g = c >> 3;
        float r = g_rstd[b][g], m = g_mean[b][g];
        float sc = gsc[c];
        coef[c] = sc * r;
        sub[c]  = gbi[c] - m * r * sc;
    }
    __syncthreads();

    __nv_bfloat16* Wp = g_wpb + (size_t)(b*3 + which) * CC * CC;
    float* bp = g_bp + (b*3 + which) * CC;

    #pragma unroll
    for (int oo = 0; oo < 4; oo++) {
        int o = obase + wid + oo * 8;
        float acc = 0.f;
        #pragma unroll
        for (int cb = 0; cb < CC; cb += 32) {
            int c = cb + lane;
            float w = W[(size_t)o * CC + c];
            Wp[(size_t)o * CC + c] = __float2bfloat16_rn(w * coef[c]);
            acc += w * sub[c];
        }
        #pragma unroll
        for (int off = 16; off; off >>= 1)
            acc += __shfl_xor_sync(~0u, acc, off);
        if (lane == 0) bp[o] = bias[o] + acc;
    }
}

// ---------------------------------------------------------------------------
// Fused QKV GEMM (bf16 MMA, ldmatrix frags, 4-stage cp.async, 2 CTAs/SM)
// O[b][n][o] = sum_c x^T[n][c] * W'[o][c] + bias'[o]
// Tile 128x128, k-step 32. grid (NQ/128, 6, B).
// ---------------------------------------------------------------------------
#define GEMM_SMEM (4 * 2 * 128 * PADK * 2)   // 4 stages x 2 ops

__global__ void __launch_bounds__(256, 2)
gemm_qkv()
{
    extern __shared__ __nv_bfloat16 smem_bf[];
    __nv_bfloat16* As = smem_bf;                    // [4][128][PADK]
    __nv_bfloat16* Bs = smem_bf + 4*128*PADK;       // [4][128][PADK]

    const int nb    = blockIdx.x * 128;
    const int which = blockIdx.y >> 1;
    const int ob    = (blockIdx.y & 1) * 128;
    const int b     = blockIdx.z;

    const __nv_bfloat16* Xt = g_xt  + (size_t)b * NQ * CC;
    const __nv_bfloat16* W  = g_wpb + (size_t)(b*3 + which) * CC * CC;
    const float* bias = g_bp + (b*3 + which) * CC;

    const int tid  = threadIdx.x;
    const int wid  = tid >> 5, lane = tid & 31;
    const int wm   = wid & 1,  wn   = wid >> 1;
    const int g    = lane >> 2, t   = lane & 3;
    const int lsel = lane & 7,  midx = lane >> 3;   // ldmatrix lane roles

    const unsigned as_base = (unsigned)__cvta_generic_to_shared(As);
    const unsigned bs_base = (unsigned)__cvta_generic_to_shared(Bs);

    const int cp_r = tid >> 2, cp_s = tid & 3;

    #define LOAD_STAGE(s, c0)                                                  \
    {                                                                          \
        _Pragma("unroll")                                                      \
        for (int j = 0; j < 2; j++) {                                          \
            int row = cp_r + j * 64;                                           \
            cp16(as_base + (((s)*128 + row) * PADK + cp_s * 8) * 2,            \
                 Xt + (size_t)(nb + row) * CC + (c0) + cp_s * 8);              \
            cp16(bs_base + (((s)*128 + row) * PADK + cp_s * 8) * 2,            \
                 W  + (size_t)(ob + row) * CC + (c0) + cp_s * 8);              \
        }                                                                      \
        CP_COMMIT();                                                           \
    }

    float acc[4][4][4];
    #pragma unroll
    for (int i = 0; i < 4; i++)
        #pragma unroll
        for (int j = 0; j < 4; j++)
            #pragma unroll
            for (int r = 0; r < 4; r++) acc[i][j][r] = 0.f;

    LOAD_STAGE(0, 0);
    LOAD_STAGE(1, 32);
    LOAD_STAGE(2, 64);

    #pragma unroll
    for (int ks = 0; ks < 8; ks++) {
        const int cur = ks & 3;
        if (ks < 6)      { CP_WAIT(2); }
        else if (ks == 6){ CP_WAIT(1); }
        else             { CP_WAIT(0); }
        __syncthreads();
        if (ks < 5) LOAD_STAGE((ks + 3) & 3, (ks + 3) * 32);

        #pragma unroll
        for (int kk = 0; kk < 2; kk++) {
            unsigned afr[4][4], bfr[4][2];
            // A: 4 fragments per ldmatrix.x4 (row-half m0/m1, k-half m2/m3)
            #pragma unroll
            for (int mt = 0; mt < 4; mt++) {
                int arow = wm*64 + mt*16 + lsel + ((midx & 1) << 3);
                int acol = kk*16 + ((midx >> 1) << 3);
                ldsm4(afr[mt][0], afr[mt][1], afr[mt][2], afr[mt][3],
                      as_base + ((cur*128 + arow) * PADK + acol) * 2);
            }
            // B: 2x ldmatrix.x4, each covering two nt (k-half m0/m1, n-half m2/m3)
            #pragma unroll
            for (int np = 0; np < 2; np++) {
                int brow = wn*32 + np*16 + lsel + ((midx >> 1) << 3);
                int bcol = kk*16 + ((midx & 1) << 3);
                ldsm4(bfr[2*np][0], bfr[2*np][1], bfr[2*np+1][0], bfr[2*np+1][1],
                      bs_base + ((cur*128 + brow) * PADK + bcol) * 2);
            }
            #pragma unroll
            for (int mt = 0; mt < 4; mt++)
                #pragma unroll
                for (int nt = 0; nt < 4; nt++)
                    mma_bf16(acc[mt][nt], afr[mt], bfr[nt]);
        }
    }
    #undef LOAD_STAGE

    __nv_bfloat16* O = (which == 0 ? g_qb : which == 1 ? g_kb : g_vb)
                       + (size_t)b * NQ * CC;
    #pragma unroll
    for (int nt = 0; nt < 4; nt++) {
        int o = ob + wn*32 + nt*8 + 2*t;
        float bb0 = bias[o], bb1 = bias[o + 1];
        #pragma unroll
        for (int mt = 0; mt < 4; mt++) {
            int n0 = nb + wm*64 + mt*16 + g;
            __nv_bfloat162 v0 = {__float2bfloat16_rn(acc[mt][nt][0] + bb0),
                                 __float2bfloat16_rn(acc[mt][nt][1] + bb1)};
            __nv_bfloat162 v1 = {__float2bfloat16_rn(acc[mt][nt][2] + bb0),
                                 __float2bfloat16_rn(acc[mt][nt][3] + bb1)};
            *(__nv_bfloat162*)&O[(size_t)n0 * CC + o]       = v0;
            *(__nv_bfloat162*)&O[(size_t)(n0 + 8) * CC + o] = v1;
        }
    }
}

// ---------------------------------------------------------------------------
// Sparse attention (round-11/12, unchanged)
// ---------------------------------------------------------------------------
__global__ void __launch_bounds__(128)
attn_kernel(const int* __restrict__ mask, const int* __restrict__ aidx)
{
    __shared__ int   sidx[4][64];
    __shared__ float sl  [4][64][4];

    const int wrp = threadIdx.x >> 5, l = threadIdx.x & 31;
    const int gw = blockIdx.x * 4 + wrp;
    const int n  = gw & (NQ - 1);
    const int b  = gw >> 12;

    const __nv_bfloat16* qp = g_qb + ((size_t)b * NQ + n) * CC;
    const __nv_bfloat16* Kb = g_kb + (size_t)b * NQ * CC;
    const __nv_bfloat16* Vb = g_vb + (size_t)b * NQ * CC;

    unsigned long long q2[4];
    {
        uint4 qw = *(const uint4*)(qp + 8 * l);
        q2[0] = bfx2(qw.x); q2[1] = bfx2(qw.y);
        q2[2] = bfx2(qw.z); q2[3] = bfx2(qw.w);
    }

    int nact;
    {
        int i0 = aidx[n * KK + l];
        int i1 = aidx[n * KK + l + 32];
        int m0 = mask[n * KK + l];
        int m1 = mask[n * KK + l + 32];
        unsigned bl0 = __ballot_sync(~0u, m0 != 0);
        unsigned bl1 = __ballot_sync(~0u, m1 != 0);
        int cnt0 = __popc(bl0);
        nact = cnt0 + __popc(bl1);
        unsigned below = (1u << l) - 1u;
        if (m0) sidx[wrp][__popc(bl0 & below)]        = i0;
        if (m1) sidx[wrp][cnt0 + __popc(bl1 & below)] = i1;
    }
    __syncwarp();

    const int h = l >> 3, i = l & 7;

    #pragma unroll 4
    for (int key = 0; key < nact; key++) {
        const int idx = sidx[wrp][key];
        uint4 kw = ((const uint4*)(Kb + (size_t)idx * CC))[l];
        unsigned long long a2 = 0ull;
        ffma2(a2, q2[0], bfx2(kw.x));
        ffma2(a2, q2[1], bfx2(kw.y));
        ffma2(a2, q2[2], bfx2(kw.z));
        ffma2(a2, q2[3], bfx2(kw.w));
        float plo, phi; upk2(a2, plo, phi);
        float p = plo + phi;
        p += __shfl_xor_sync(~0u, p, 4);
        p += __shfl_xor_sync(~0u, p, 2);
        p += __shfl_xor_sync(~0u, p, 1);
        if (i == (key & 7)) sl[wrp][key][h] = p;
    }
    __syncwarp();

    float lg[8];
    #pragma unroll
    for (int j = 0; j < 8; j++) {
        int key = i + 8 * j;
        lg[j] = (key < nact) ? sl[wrp][key][h] : -INFINITY;
    }
    float mx = lg[0];
    #pragma unroll
    for (int j = 1; j < 8; j++) mx = fmaxf(mx, lg[j]);
    mx = fmaxf(mx, __shfl_xor_sync(~0u, mx, 4));
    mx = fmaxf(mx, __shfl_xor_sync(~0u, mx, 2));
    mx = fmaxf(mx, __shfl_xor_sync(~0u, mx, 1));

    float e[8], s = 0.f;
    #pragma unroll
    for (int j = 0; j < 8; j++) { e[j] = __expf(lg[j] - mx); s += e[j]; }
    s += __shfl_xor_sync(~0u, s, 4);
    s += __shfl_xor_sync(~0u, s, 2);
    s += __shfl_xor_sync(~0u, s, 1);
    const float inv = 1.f / s;

    #pragma unroll
    for (int j = 0; j < 8; j++)
        sl[wrp][i + 8 * j][h] = e[j] * inv;
    __syncwarp();

    unsigned long long vacc[4] = {0ull, 0ull, 0ull, 0ull};

    #pragma unroll 4
    for (int key = 0; key < nact; key++) {
        const int idx = sidx[wrp][key];
        const float wv = sl[wrp][key][h];
        unsigned wu = __float_as_uint(wv);
        unsigned long long w2 = pk2(wu, wu);
        uint4 vw = ((const uint4*)(Vb + (size_t)idx * CC))[l];
        ffma2(vacc[0], w2, bfx2(vw.x));
        ffma2(vacc[1], w2, bfx2(vw.y));
        ffma2(vacc[2], w2, bfx2(vw.z));
        ffma2(vacc[3], w2, bfx2(vw.w));
    }

    float acc[8];
    upk2(vacc[0], acc[0], acc[1]);
    upk2(vacc[1], acc[2], acc[3]);
    upk2(vacc[2], acc[4], acc[5]);
    upk2(vacc[3], acc[6], acc[7]);

    __nv_bfloat16* at = g_atb + ((size_t)b * NQ + n) * CC;
    #pragma unroll
    for (int j = 0; j < 8; j++) {
        int c = 8 * l + j;                   // c = 64*h + d
        at[(c & 63) * HEADS + h] = __float2bfloat16_rn(acc[j]);
    }
}

// ---------------------------------------------------------------------------
// Output projection + residual (bf16 MMA, ldmatrix frags, 4-stage, 2 CTAs/SM)
// ---------------------------------------------------------------------------
__global__ void __launch_bounds__(256, 2)
gemm_out(const float* __restrict__ bo,
         const float* __restrict__ x,  float* __restrict__ out)
{
    extern __shared__ __nv_bfloat16 smem_bf[];
    __nv_bfloat16* As = smem_bf;                    // [4][128][PADK] Wo
    __nv_bfloat16* Bs = smem_bf + 4*128*PADK;       // [4][128][PADK] at

    const int nb = blockIdx.x * 128, ob = blockIdx.y * 128, b = blockIdx.z;
    const __nv_bfloat16* A = g_atb + (size_t)b * NQ * CC;

    const int tid  = threadIdx.x;
    const int wid  = tid >> 5, lane = tid & 31;
    const int wm   = wid & 1,  wn   = wid >> 1;
    const int g    = lane >> 2, t   = lane & 3;
    const int lsel = lane & 7,  midx = lane >> 3;

    const unsigned as_base = (unsigned)__cvta_generic_to_shared(As);
    const unsigned bs_base = (unsigned)__cvta_generic_to_shared(Bs);

    const int cp_r = tid >> 2, cp_s = tid & 3;

    #define LOAD_STAGE(s, c0)                                                  \
    {                                                                          \
        _Pragma("unroll")                                                      \
        for (int j = 0; j < 2; j++) {                                          \
            int row = cp_r + j * 64;                                           \
            cp16(as_base + (((s)*128 + row) * PADK + cp_s * 8) * 2,            \
                 g_wob + (size_t)(ob + row) * CC + (c0) + cp_s * 8);           \
            cp16(bs_base + (((s)*128 + row) * PADK + cp_s * 8) * 2,            \
                 A + (size_t)(nb + row) * CC + (c0) + cp_s * 8);               \
        }                                                                      \
        CP_COMMIT();                                                           \
    }

    float acc[4][4][4];
    #pragma unroll
    for (int i = 0; i < 4; i++)
        #pragma unroll
        for (int j = 0; j < 4; j++)
            #pragma unroll
            for (int r = 0; r < 4; r++) acc[i][j][r] = 0.f;

    LOAD_STAGE(0, 0);
    LOAD_STAGE(1, 32);
    LOAD_STAGE(2, 64);

    #pragma unroll
    for (int ks = 0; ks < 8; ks++) {
        const int cur = ks & 3;
        if (ks < 6)      { CP_WAIT(2); }
        else if (ks == 6){ CP_WAIT(1); }
        else             { CP_WAIT(0); }
        __syncthreads();
        if (ks < 5) LOAD_STAGE((ks + 3) & 3, (ks + 3) * 32);

        #pragma unroll
        for (int kk = 0; kk < 2; kk++) {
            unsigned afr[4][4], bfr[4][2];
            #pragma unroll
            for (int mt = 0; mt < 4; mt++) {
                int arow = wm*64 + mt*16 + lsel + ((midx & 1) << 3);
                int acol = kk*16 + ((midx >> 1) << 3);
                ldsm4(afr[mt][0], afr[mt][1], afr[mt][2], afr[mt][3],
                      as_base + ((cur*128 + arow) * PADK + acol) * 2);
            }
            #pragma unroll
            for (int np = 0; np < 2; np++) {
                int brow = wn*32 + np*16 + lsel + ((midx >> 1) << 3);
                int bcol = kk*16 + ((midx & 1) << 3);
                ldsm4(bfr[2*np][0], bfr[2*np][1], bfr[2*np+1][0], bfr[2*np+1][1],
                      bs_base + ((cur*128 + brow) * PADK + bcol) * 2);
            }
            #pragma unroll
            for (int mt = 0; mt < 4; mt++)
                #pragma unroll
                for (int nt = 0; nt < 4; nt++)
                    mma_bf16(acc[mt][nt], afr[mt], bfr[nt]);
        }
    }
    #undef LOAD_STAGE

    const float* xp = x   + (size_t)b * CC * NQ;
    float*       op = out + (size_t)b * CC * NQ;
    #pragma unroll
    for (int mt = 0; mt < 4; mt++) {
        int o0 = ob + wm*64 + mt*16 + g;
        float bb0 = bo[o0], bb1 = bo[o0 + 8];
        #pragma unroll
        for (int nt = 0; nt < 4; nt++) {
            int n = nb + wn*32 + nt*8 + 2*t;
            size_t base0 = (size_t)o0 * NQ + n;
            size_t base1 = (size_t)(o0 + 8) * NQ + n;
            float2 x0 = *(const float2*)&xp[base0];
            float2 x1 = *(const float2*)&xp[base1];
            float2 v0 = {acc[mt][nt][0] + bb0 + x0.x, acc[mt][nt][1] + bb0 + x0.y};
            float2 v1 = {acc[mt][nt][2] + bb1 + x1.x, acc[mt][nt][3] + bb1 + x1.y};
            *(float2*)&op[base0] = v0;
            *(float2*)&op[base1] = v1;
        }
    }
}

// ---------------------------------------------------------------------------
extern "C" void kernel_launch(void* const* d_in, const int* in_sizes, int n_in,
                              void* d_out, int out_size)
{
    const float* x    = (const float*)d_in[0];
    const int*   mask = (const int*)  d_in[1];
    const int*   aidx = (const int*)  d_in[2];
    const float* gsc  = (const float*)d_in[3];
    const float* gbi  = (const float*)d_in[4];
    const float* wq   = (const float*)d_in[5];
    const float* bq   = (const float*)d_in[6];
    const float* wk   = (const float*)d_in[7];
    const float* bk   = (const float*)d_in[8];
    const float* wv   = (const float*)d_in[9];
    const float* bv   = (const float*)d_in[10];
    const float* wo   = (const float*)d_in[11];
    const float* bo   = (const float*)d_in[12];
    float* out = (float*)d_out;

    cudaFuncSetAttribute(gemm_qkv, cudaFuncAttributeMaxDynamicSharedMemorySize,
                         GEMM_SMEM);
    cudaFuncSetAttribute(gemm_out, cudaFuncAttributeMaxDynamicSharedMemorySize,
                         GEMM_SMEM);

    xpose_gn<<<dim3(NQ / 32, CC / 32, BB), dim3(32, 8)>>>(x);

    gn_finish<<<dim3(GROUPS, BB), 128>>>();

    wprep<<<dim3(4, BB, 8), 256>>>(wq, bq, wk, bk, wv, bv, wo, gsc, gbi);

    gemm_qkv<<<dim3(NQ / 128, 6, BB), 256, GEMM_SMEM>>>();

    attn_kernel<<<BB * NQ / 4, 128>>>(mask, aidx);

    gemm_out<<<dim3(NQ / 128, CC / 128, BB), 256, GEMM_SMEM>>>(bo, x, out);
}

// round 16
// speedup vs baseline: 1.0895x; 1.0080x over previous
#include <cuda_runtime.h>
#include <cuda_bf16.h>
#include <math.h>

#define BB     2
#define CC     256
#define NQ     4096
#define HEADS  4
#define DH     64
#define KK     64
#define GROUPS 32
#define CPG    8
#define EPS    1e-6f

#define PADK   40       // bf16 elems per k=32 smem row (80B): conflict-free frags
#define NTILES (NQ/32)  // 128 n-tiles for gn partials

// Scratch (device globals; no allocation allowed)
__device__ __nv_bfloat16 g_xt [BB*NQ*CC];   // x^T bf16, [b][n][c]
__device__ __nv_bfloat16 g_qb [BB*NQ*CC];   // Q bf16, [b][n][c]  c = head*64 + d
__device__ __nv_bfloat16 g_kb [BB*NQ*CC];   // K bf16, [b][n][c]
__device__ __nv_bfloat16 g_vb [BB*NQ*CC];   // V bf16, [b][n][c]
__device__ __nv_bfloat16 g_atb[BB*NQ*CC];   // attn out bf16, [b][n][c] c=d*HEADS+h
__device__ float         g_ps [BB*GROUPS*NTILES];   // gn partial sums
__device__ float         g_ps2[BB*GROUPS*NTILES];   // gn partial sumsq
__device__ __nv_bfloat16 g_wpb[BB*3*CC*CC]; // GN-folded qkv weights bf16
__device__ __nv_bfloat16 g_wob[CC*CC];      // Wo bf16 [o][c]
__device__ float         g_bp [BB*3*CC];    // GN-folded biases fp32

// ---------------------------------------------------------------------------
// helpers
// ---------------------------------------------------------------------------
__device__ __forceinline__ void mma_bf16(float d[4], const unsigned a[4],
                                         const unsigned b[2]) {
    asm("mma.sync.aligned.m16n8k16.row.col.f32.bf16.bf16.f32 "
        "{%0,%1,%2,%3}, {%4,%5,%6,%7}, {%8,%9}, {%0,%1,%2,%3};"
        : "+f"(d[0]), "+f"(d[1]), "+f"(d[2]), "+f"(d[3])
        : "r"(a[0]), "r"(a[1]), "r"(a[2]), "r"(a[3]),
          "r"(b[0]), "r"(b[1]));
}

__device__ __forceinline__ void cp16(unsigned dst, const void* src) {
    asm volatile("cp.async.cg.shared.global [%0], [%1], 16;"
                 :: "r"(dst), "l"(src));
}
#define CP_COMMIT() asm volatile("cp.async.commit_group;")
#define CP_WAIT(n)  asm volatile("cp.async.wait_group %0;" :: "n"(n))

// packed f32x2 helpers (sm_103a dual-f32 pipe)
__device__ __forceinline__ unsigned long long pk2(unsigned lo, unsigned hi) {
    unsigned long long r;
    asm("mov.b64 %0, {%1,%2};" : "=l"(r) : "r"(lo), "r"(hi));
    return r;
}
__device__ __forceinline__ void upk2(unsigned long long v, float& lo, float& hi) {
    unsigned a, b;
    asm("mov.b64 {%0,%1}, %2;" : "=r"(a), "=r"(b) : "l"(v));
    lo = __uint_as_float(a); hi = __uint_as_float(b);
}
__device__ __forceinline__ unsigned long long bfx2(unsigned u) {
    return pk2(u << 16, u & 0xFFFF0000u);   // bf16x2 -> packed f32x2
}
__device__ __forceinline__ void ffma2(unsigned long long& d,
                                      unsigned long long a,
                                      unsigned long long b) {
    asm("fma.rn.f32x2 %0, %1, %2, %0;" : "+l"(d) : "l"(a), "l"(b));
}

// ---------------------------------------------------------------------------
// Fused transpose + GN partial stats
// ---------------------------------------------------------------------------
__global__ void xpose_gn(const float* __restrict__ x)
{
    __shared__ float t[32][33];
    __shared__ float red[8][4][2];
    const int b = blockIdx.z;
    const int n0 = blockIdx.x * 32, c0 = blockIdx.y * 32;
    const float* xp = x + (size_t)b * CC * NQ;
    const int tx = threadIdx.x, ty = threadIdx.y;

    float vs[4];
    #pragma unroll
    for (int k = 0; k < 4; k++) {
        int cl = k * 8 + ty;
        float v = xp[(size_t)(c0 + cl) * NQ + n0 + tx];
        t[cl][tx] = v;
        vs[k] = v;
    }
    #pragma unroll
    for (int k = 0; k < 4; k++) {
        float s = vs[k], s2 = vs[k] * vs[k];
        #pragma unroll
        for (int o = 16; o; o >>= 1) {
            s  += __shfl_xor_sync(~0u, s,  o);
            s2 += __shfl_xor_sync(~0u, s2, o);
        }
        if (tx == 0) { red[ty][k][0] = s; red[ty][k][1] = s2; }
    }
    __syncthreads();

    __nv_bfloat16* o = g_xt + (size_t)b * NQ * CC;
    #pragma unroll
    for (int k = 0; k < 4; k++) {
        int nl = k * 8 + ty;
        o[(size_t)(n0 + nl) * CC + c0 + tx] = __float2bfloat16_rn(t[tx][nl]);
    }

    if (ty == 0 && tx < 4) {
        float s = 0.f, s2 = 0.f;
        #pragma unroll
        for (int y = 0; y < 8; y++) { s += red[y][tx][0]; s2 += red[y][tx][1]; }
        int grp = blockIdx.y * 4 + tx;
        g_ps [(b * GROUPS + grp) * NTILES + blockIdx.x] = s;
        g_ps2[(b * GROUPS + grp) * NTILES + blockIdx.x] = s2;
    }
}

// ---------------------------------------------------------------------------
// Weight prep with inline GN-stats reduction (gn_finish folded in).
// grid (4, B, 8), block 256.
// ---------------------------------------------------------------------------
__global__ void wprep(const float* __restrict__ wq, const float* __restrict__ bq,
                      const float* __restrict__ wk, const float* __restrict__ bk,
                      const float* __restrict__ wv, const float* __restrict__ bv,
                      const float* __restrict__ wo,
                      const float* __restrict__ gsc, const float* __restrict__ gbi)
{
    const int which = blockIdx.x, b = blockIdx.y;
    const int obase = blockIdx.z * 32;
    const int tid = threadIdx.x;
    const int wid = tid >> 5, lane = tid & 31;

    if (which == 3) {
        #pragma unroll
        for (int oo = 0; oo < 4; oo++) {
            int o = obase + wid + oo * 8;
            #pragma unroll
            for (int cb = 0; cb < CC; cb += 32) {
                int c = cb + lane;
                g_wob[(size_t)o * CC + c] =
                    __float2bfloat16_rn(wo[(size_t)o * CC + c]);
            }
        }
        return;
    }

    const float* W    = which == 0 ? wq : which == 1 ? wk : wv;
    const float* bias = which == 0 ? bq : which == 1 ? bk : bv;

    __shared__ float mean_s[GROUPS], rstd_s[GROUPS];
    __shared__ float coef[CC], sub[CC];

    // inline stats: group g = tid>>3, sub-lane i = tid&7 reduces 16 partials
    {
        int g = tid >> 3, i = tid & 7;
        const float* ps  = g_ps  + (b * GROUPS + g) * NTILES + i * 16;
        const float* ps2 = g_ps2 + (b * GROUPS + g) * NTILES + i * 16;
        float s = 0.f, s2 = 0.f;
        #pragma unroll
        for (int j = 0; j < 16; j++) { s += ps[j]; s2 += ps2[j]; }
        s  += __shfl_xor_sync(~0u, s,  4);
        s2 += __shfl_xor_sync(~0u, s2, 4);
        s  += __shfl_xor_sync(~0u, s,  2);
        s2 += __shfl_xor_sync(~0u, s2, 2);
        s  += __shfl_xor_sync(~0u, s,  1);
        s2 += __shfl_xor_sync(~0u, s2, 1);
        if (i == 0) {
            const float NE = (float)(CPG * NQ);
            float m = s / NE;
            float var = s2 / NE - m * m;
            mean_s[g] = m;
            rstd_s[g] = rsqrtf(var + EPS);
        }
    }
    __syncthreads();
    {
        int c = tid;
        int g = c >> 3;
        float r = rstd_s[g], m = mean_s[g];
        float sc = gsc[c];
        coef[c] = sc * r;
        sub[c]  = gbi[c] - m * r * sc;
    }
    __syncthreads();

    __nv_bfloat16* Wp = g_wpb + (size_t)(b*3 + which) * CC * CC;
    float* bp = g_bp + (b*3 + which) * CC;

    #pragma unroll
    for (int oo = 0; oo < 4; oo++) {
        int o = obase + wid + oo * 8;
        float acc = 0.f;
        #pragma unroll
        for (int cb = 0; cb < CC; cb += 32) {
            int c = cb + lane;
            float w = W[(size_t)o * CC + c];
            Wp[(size_t)o * CC + c] = __float2bfloat16_rn(w * coef[c]);
            acc += w * sub[c];
        }
        #pragma unroll
        for (int off = 16; off; off >>= 1)
            acc += __shfl_xor_sync(~0u, acc, off);
        if (lane == 0) bp[o] = bias[o] + acc;
    }
}

// ---------------------------------------------------------------------------
// Fused QKV GEMM (bf16 MMA, 4-stage cp.async, ONE sync per k-step, 2 CTAs/SM)
// O[b][n][o] = sum_c x^T[n][c] * W'[o][c] + bias'[o]
// Tile 128x128, k-step 32. grid (NQ/128, 6, B).
// ---------------------------------------------------------------------------
#define GEMM_SMEM (4 * 2 * 128 * PADK * 2)   // 4 stages x 2 ops

__global__ void __launch_bounds__(256, 2)
gemm_qkv()
{
    extern __shared__ __nv_bfloat16 smem_bf[];
    __nv_bfloat16* As = smem_bf;                    // [4][128][PADK]
    __nv_bfloat16* Bs = smem_bf + 4*128*PADK;       // [4][128][PADK]
    const unsigned* As32 = (const unsigned*)As;
    const unsigned* Bs32 = (const unsigned*)Bs;

    const int nb    = blockIdx.x * 128;
    const int which = blockIdx.y >> 1;
    const int ob    = (blockIdx.y & 1) * 128;
    const int b     = blockIdx.z;

    const __nv_bfloat16* Xt = g_xt  + (size_t)b * NQ * CC;
    const __nv_bfloat16* W  = g_wpb + (size_t)(b*3 + which) * CC * CC;
    const float* bias = g_bp + (b*3 + which) * CC;

    const int tid  = threadIdx.x;
    const int wid  = tid >> 5, lane = tid & 31;
    const int wm   = wid & 1,  wn   = wid >> 1;
    const int g    = lane >> 2, t   = lane & 3;

    const unsigned as_base = (unsigned)__cvta_generic_to_shared(As);
    const unsigned bs_base = (unsigned)__cvta_generic_to_shared(Bs);

    const int cp_r = tid >> 2, cp_s = tid & 3;

    #define LOAD_STAGE(s, c0)                                                  \
    {                                                                          \
        _Pragma("unroll")                                                      \
        for (int j = 0; j < 2; j++) {                                          \
            int row = cp_r + j * 64;                                           \
            cp16(as_base + (((s)*128 + row) * PADK + cp_s * 8) * 2,            \
                 Xt + (size_t)(nb + row) * CC + (c0) + cp_s * 8);              \
            cp16(bs_base + (((s)*128 + row) * PADK + cp_s * 8) * 2,            \
                 W  + (size_t)(ob + row) * CC + (c0) + cp_s * 8);              \
        }                                                                      \
        CP_COMMIT();                                                           \
    }

    float acc[4][4][4];
    #pragma unroll
    for (int i = 0; i < 4; i++)
        #pragma unroll
        for (int j = 0; j < 4; j++)
            #pragma unroll
            for (int r = 0; r < 4; r++) acc[i][j][r] = 0.f;

    LOAD_STAGE(0, 0);
    LOAD_STAGE(1, 32);
    LOAD_STAGE(2, 64);

    #pragma unroll
    for (int ks = 0; ks < 8; ks++) {
        const int cur = ks & 3;
        if (ks < 6)      { CP_WAIT(2); }
        else if (ks == 6){ CP_WAIT(1); }
        else             { CP_WAIT(0); }
        __syncthreads();
        if (ks < 5) LOAD_STAGE((ks + 3) & 3, (ks + 3) * 32);

        #pragma unroll
        for (int kk = 0; kk < 2; kk++) {
            unsigned afr[4][4], bfr[4][2];
            #pragma unroll
            for (int mt = 0; mt < 4; mt++) {
                int base = (cur*128 + wm*64 + mt*16 + g) * (PADK/2) + kk*8 + t;
                afr[mt][0] = As32[base];
                afr[mt][1] = As32[base + 8*(PADK/2)];
                afr[mt][2] = As32[base + 4];
                afr[mt][3] = As32[base + 8*(PADK/2) + 4];
            }
            #pragma unroll
            for (int nt = 0; nt < 4; nt++) {
                int base = (cur*128 + wn*32 + nt*8 + g) * (PADK/2) + kk*8 + t;
                bfr[nt][0] = Bs32[base];
                bfr[nt][1] = Bs32[base + 4];
            }
            #pragma unroll
            for (int mt = 0; mt < 4; mt++)
                #pragma unroll
                for (int nt = 0; nt < 4; nt++)
                    mma_bf16(acc[mt][nt], afr[mt], bfr[nt]);
        }
    }
    #undef LOAD_STAGE

    __nv_bfloat16* O = (which == 0 ? g_qb : which == 1 ? g_kb : g_vb)
                       + (size_t)b * NQ * CC;
    #pragma unroll
    for (int nt = 0; nt < 4; nt++) {
        int o = ob + wn*32 + nt*8 + 2*t;
        float bb0 = bias[o], bb1 = bias[o + 1];
        #pragma unroll
        for (int mt = 0; mt < 4; mt++) {
            int n0 = nb + wm*64 + mt*16 + g;
            __nv_bfloat162 v0 = {__float2bfloat16_rn(acc[mt][nt][0] + bb0),
                                 __float2bfloat16_rn(acc[mt][nt][1] + bb1)};
            __nv_bfloat162 v1 = {__float2bfloat16_rn(acc[mt][nt][2] + bb0),
                                 __float2bfloat16_rn(acc[mt][nt][3] + bb1)};
            *(__nv_bfloat162*)&O[(size_t)n0 * CC + o]       = v0;
            *(__nv_bfloat162*)&O[(size_t)(n0 + 8) * CC + o] = v1;
        }
    }
}

// ---------------------------------------------------------------------------
// Sparse attention: 128-thread blocks, packed f32x2 FMA
// ---------------------------------------------------------------------------
__global__ void __launch_bounds__(128)
attn_kernel(const int* __restrict__ mask, const int* __restrict__ aidx)
{
    __shared__ int   sidx[4][64];
    __shared__ float sl  [4][64][4];

    const int wrp = threadIdx.x >> 5, l = threadIdx.x & 31;
    const int gw = blockIdx.x * 4 + wrp;
    const int n  = gw & (NQ - 1);
    const int b  = gw >> 12;

    const __nv_bfloat16* qp = g_qb + ((size_t)b * NQ + n) * CC;
    const __nv_bfloat16* Kb = g_kb + (size_t)b * NQ * CC;
    const __nv_bfloat16* Vb = g_vb + (size_t)b * NQ * CC;

    unsigned long long q2[4];
    {
        uint4 qw = *(const uint4*)(qp + 8 * l);
        q2[0] = bfx2(qw.x); q2[1] = bfx2(qw.y);
        q2[2] = bfx2(qw.z); q2[3] = bfx2(qw.w);
    }

    int nact;
    {
        int i0 = aidx[n * KK + l];
        int i1 = aidx[n * KK + l + 32];
        int m0 = mask[n * KK + l];
        int m1 = mask[n * KK + l + 32];
        unsigned bl0 = __ballot_sync(~0u, m0 != 0);
        unsigned bl1 = __ballot_sync(~0u, m1 != 0);
        int cnt0 = __popc(bl0);
        nact = cnt0 + __popc(bl1);
        unsigned below = (1u << l) - 1u;
        if (m0) sidx[wrp][__popc(bl0 & below)]        = i0;
        if (m1) sidx[wrp][cnt0 + __popc(bl1 & below)] = i1;
    }
    __syncwarp();

    const int h = l >> 3, i = l & 7;

    #pragma unroll 4
    for (int key = 0; key < nact; key++) {
        const int idx = sidx[wrp][key];
        uint4 kw = ((const uint4*)(Kb + (size_t)idx * CC))[l];
        unsigned long long a2 = 0ull;
        ffma2(a2, q2[0], bfx2(kw.x));
        ffma2(a2, q2[1], bfx2(kw.y));
        ffma2(a2, q2[2], bfx2(kw.z));
        ffma2(a2, q2[3], bfx2(kw.w));
        float plo, phi; upk2(a2, plo, phi);
        float p = plo + phi;
        p += __shfl_xor_sync(~0u, p, 4);
        p += __shfl_xor_sync(~0u, p, 2);
        p += __shfl_xor_sync(~0u, p, 1);
        if (i == (key & 7)) sl[wrp][key][h] = p;
    }
    __syncwarp();

    float lg[8];
    #pragma unroll
    for (int j = 0; j < 8; j++) {
        int key = i + 8 * j;
        lg[j] = (key < nact) ? sl[wrp][key][h] : -INFINITY;
    }
    float mx = lg[0];
    #pragma unroll
    for (int j = 1; j < 8; j++) mx = fmaxf(mx, lg[j]);
    mx = fmaxf(mx, __shfl_xor_sync(~0u, mx, 4));
    mx = fmaxf(mx, __shfl_xor_sync(~0u, mx, 2));
    mx = fmaxf(mx, __shfl_xor_sync(~0u, mx, 1));

    float e[8], s = 0.f;
    #pragma unroll
    for (int j = 0; j < 8; j++) { e[j] = __expf(lg[j] - mx); s += e[j]; }
    s += __shfl_xor_sync(~0u, s, 4);
    s += __shfl_xor_sync(~0u, s, 2);
    s += __shfl_xor_sync(~0u, s, 1);
    const float inv = 1.f / s;

    #pragma unroll
    for (int j = 0; j < 8; j++)
        sl[wrp][i + 8 * j][h] = e[j] * inv;
    __syncwarp();

    unsigned long long vacc[4] = {0ull, 0ull, 0ull, 0ull};

    #pragma unroll 4
    for (int key = 0; key < nact; key++) {
        const int idx = sidx[wrp][key];
        const float wv = sl[wrp][key][h];
        unsigned wu = __float_as_uint(wv);
        unsigned long long w2 = pk2(wu, wu);
        uint4 vw = ((const uint4*)(Vb + (size_t)idx * CC))[l];
        ffma2(vacc[0], w2, bfx2(vw.x));
        ffma2(vacc[1], w2, bfx2(vw.y));
        ffma2(vacc[2], w2, bfx2(vw.z));
        ffma2(vacc[3], w2, bfx2(vw.w));
    }

    float acc[8];
    upk2(vacc[0], acc[0], acc[1]);
    upk2(vacc[1], acc[2], acc[3]);
    upk2(vacc[2], acc[4], acc[5]);
    upk2(vacc[3], acc[6], acc[7]);

    __nv_bfloat16* at = g_atb + ((size_t)b * NQ + n) * CC;
    #pragma unroll
    for (int j = 0; j < 8; j++) {
        int c = 8 * l + j;                   // c = 64*h + d
        at[(c & 63) * HEADS + h] = __float2bfloat16_rn(acc[j]);
    }
}

// ---------------------------------------------------------------------------
// Output projection + residual (bf16 MMA, 4-stage cp.async, one sync/step)
// ---------------------------------------------------------------------------
__global__ void __launch_bounds__(256, 2)
gemm_out(const float* __restrict__ bo,
         const float* __restrict__ x,  float* __restrict__ out)
{
    extern __shared__ __nv_bfloat16 smem_bf[];
    __nv_bfloat16* As = smem_bf;                    // [4][128][PADK] Wo
    __nv_bfloat16* Bs = smem_bf + 4*128*PADK;       // [4][128][PADK] at
    const unsigned* As32 = (const unsigned*)As;
    const unsigned* Bs32 = (const unsigned*)Bs;

    const int nb = blockIdx.x * 128, ob = blockIdx.y * 128, b = blockIdx.z;
    const __nv_bfloat16* A = g_atb + (size_t)b * NQ * CC;

    const int tid  = threadIdx.x;
    const int wid  = tid >> 5, lane = tid & 31;
    const int wm   = wid & 1,  wn   = wid >> 1;
    const int g    = lane >> 2, t   = lane & 3;

    const unsigned as_base = (unsigned)__cvta_generic_to_shared(As);
    const unsigned bs_base = (unsigned)__cvta_generic_to_shared(Bs);

    const int cp_r = tid >> 2, cp_s = tid & 3;

    #define LOAD_STAGE(s, c0)                                                  \
    {                                                                          \
        _Pragma("unroll")                                                      \
        for (int j = 0; j < 2; j++) {                                          \
            int row = cp_r + j * 64;                                           \
            cp16(as_base + (((s)*128 + row) * PADK + cp_s * 8) * 2,            \
                 g_wob + (size_t)(ob + row) * CC + (c0) + cp_s * 8);           \
            cp16(bs_base + (((s)*128 + row) * PADK + cp_s * 8) * 2,            \
                 A + (size_t)(nb + row) * CC + (c0) + cp_s * 8);               \
        }                                                                      \
        CP_COMMIT();                                                           \
    }

    float acc[4][4][4];
    #pragma unroll
    for (int i = 0; i < 4; i++)
        #pragma unroll
        for (int j = 0; j < 4; j++)
            #pragma unroll
            for (int r = 0; r < 4; r++) acc[i][j][r] = 0.f;

    LOAD_STAGE(0, 0);
    LOAD_STAGE(1, 32);
    LOAD_STAGE(2, 64);

    #pragma unroll
    for (int ks = 0; ks < 8; ks++) {
        const int cur = ks & 3;
        if (ks < 6)      { CP_WAIT(2); }
        else if (ks == 6){ CP_WAIT(1); }
        else             { CP_WAIT(0); }
        __syncthreads();
        if (ks < 5) LOAD_STAGE((ks + 3) & 3, (ks + 3) * 32);

        #pragma unroll
        for (int kk = 0; kk < 2; kk++) {
            unsigned afr[4][4], bfr[4][2];
            #pragma unroll
            for (int mt = 0; mt < 4; mt++) {
                int base = (cur*128 + wm*64 + mt*16 + g) * (PADK/2) + kk*8 + t;
                afr[mt][0] = As32[base];
                afr[mt][1] = As32[base + 8*(PADK/2)];
                afr[mt][2] = As32[base + 4];
                afr[mt][3] = As32[base + 8*(PADK/2) + 4];
            }
            #pragma unroll
            for (int nt = 0; nt < 4; nt++) {
                int base = (cur*128 + wn*32 + nt*8 + g) * (PADK/2) + kk*8 + t;
                bfr[nt][0] = Bs32[base];
                bfr[nt][1] = Bs32[base + 4];
            }
            #pragma unroll
            for (int mt = 0; mt < 4; mt++)
                #pragma unroll
                for (int nt = 0; nt < 4; nt++)
                    mma_bf16(acc[mt][nt], afr[mt], bfr[nt]);
        }
    }
    #undef LOAD_STAGE

    const float* xp = x   + (size_t)b * CC * NQ;
    float*       op = out + (size_t)b * CC * NQ;
    #pragma unroll
    for (int mt = 0; mt < 4; mt++) {
        int o0 = ob + wm*64 + mt*16 + g;
        float bb0 = bo[o0], bb1 = bo[o0 + 8];
        #pragma unroll
        for (int nt = 0; nt < 4; nt++) {
            int n = nb + wn*32 + nt*8 + 2*t;
            size_t base0 = (size_t)o0 * NQ + n;
            size_t base1 = (size_t)(o0 + 8) * NQ + n;
            float2 x0 = *(const float2*)&xp[base0];
            float2 x1 = *(const float2*)&xp[base1];
            float2 v0 = {acc[mt][nt][0] + bb0 + x0.x, acc[mt][nt][1] + bb0 + x0.y};
            float2 v1 = {acc[mt][nt][2] + bb1 + x1.x, acc[mt][nt][3] + bb1 + x1.y};
            *(float2*)&op[base0] = v0;
            *(float2*)&op[base1] = v1;
        }
    }
}

// ---------------------------------------------------------------------------
extern "C" void kernel_launch(void* const* d_in, const int* in_sizes, int n_in,
                              void* d_out, int out_size)
{
    const float* x    = (const float*)d_in[0];
    const int*   mask = (const int*)  d_in[1];
    const int*   aidx = (const int*)  d_in[2];
    const float* gsc  = (const float*)d_in[3];
    const float* gbi  = (const float*)d_in[4];
    const float* wq   = (const float*)d_in[5];
    const float* bq   = (const float*)d_in[6];
    const float* wk   = (const float*)d_in[7];
    const float* bk   = (const float*)d_in[8];
    const float* wv   = (const float*)d_in[9];
    const float* bv   = (const float*)d_in[10];
    const float* wo   = (const float*)d_in[11];
    const float* bo   = (const float*)d_in[12];
    float* out = (float*)d_out;

    cudaFuncSetAttribute(gemm_qkv, cudaFuncAttributeMaxDynamicSharedMemorySize,
                         GEMM_SMEM);
    cudaFuncSetAttribute(gemm_out, cudaFuncAttributeMaxDynamicSharedMemorySize,
                         GEMM_SMEM);

    xpose_gn<<<dim3(NQ / 32, CC / 32, BB), dim3(32, 8)>>>(x);

    wprep<<<dim3(4, BB, 8), 256>>>(wq, bq, wk, bk, wv, bv, wo, gsc, gbi);

    gemm_qkv<<<dim3(NQ / 128, 6, BB), 256, GEMM_SMEM>>>();

    attn_kernel<<<BB * NQ / 4, 128>>>(mask, aidx);

    gemm_out<<<dim3(NQ / 128, CC / 128, BB), 256, GEMM_SMEM>>>(bo, x, out);
}

// round 17
// speedup vs baseline: 1.0900x; 1.0005x over previous
#include <cuda_runtime.h>
#include <cuda_bf16.h>
#include <math.h>

#define BB     2
#define CC     256
#define NQ     4096
#define HEADS  4
#define DH     64
#define KK     64
#define GROUPS 32
#define CPG    8
#define EPS    1e-6f

#define PADK   40       // bf16 elems per k=32 smem row (80B): conflict-free frags
#define NTILES (NQ/32)  // 128 n-tiles for gn partials

// Scratch (device globals; no allocation allowed)
__device__ __nv_bfloat16 g_xt [BB*NQ*CC];   // x^T bf16, [b][n][c]
__device__ __nv_bfloat16 g_qb [BB*NQ*CC];   // Q bf16, [b][n][c]  c = head*64 + d
__device__ __nv_bfloat16 g_kb [BB*NQ*CC];   // K bf16, [b][n][c]
__device__ __nv_bfloat16 g_vb [BB*NQ*CC];   // V bf16, [b][n][c]
__device__ __nv_bfloat16 g_atb[BB*NQ*CC];   // attn out bf16, [b][n][c] c=d*HEADS+h
__device__ float         g_ps [BB*GROUPS*NTILES];   // gn partial sums
__device__ float         g_ps2[BB*GROUPS*NTILES];   // gn partial sumsq
__device__ __nv_bfloat16 g_wpb[BB*3*CC*CC]; // GN-folded qkv weights bf16
__device__ __nv_bfloat16 g_wob[CC*CC];      // Wo bf16 [o][c]
__device__ float         g_bp [BB*3*CC];    // GN-folded biases fp32

// ---------------------------------------------------------------------------
// helpers
// ---------------------------------------------------------------------------
__device__ __forceinline__ void mma_bf16(float d[4], const unsigned a[4],
                                         const unsigned b[2]) {
    asm("mma.sync.aligned.m16n8k16.row.col.f32.bf16.bf16.f32 "
        "{%0,%1,%2,%3}, {%4,%5,%6,%7}, {%8,%9}, {%0,%1,%2,%3};"
        : "+f"(d[0]), "+f"(d[1]), "+f"(d[2]), "+f"(d[3])
        : "r"(a[0]), "r"(a[1]), "r"(a[2]), "r"(a[3]),
          "r"(b[0]), "r"(b[1]));
}

__device__ __forceinline__ void cp16(unsigned dst, const void* src) {
    asm volatile("cp.async.cg.shared.global [%0], [%1], 16;"
                 :: "r"(dst), "l"(src));
}
#define CP_COMMIT() asm volatile("cp.async.commit_group;")
#define CP_WAIT(n)  asm volatile("cp.async.wait_group %0;" :: "n"(n))

// packed f32x2 helpers (sm_103a dual-f32 pipe)
__device__ __forceinline__ unsigned long long pk2(unsigned lo, unsigned hi) {
    unsigned long long r;
    asm("mov.b64 %0, {%1,%2};" : "=l"(r) : "r"(lo), "r"(hi));
    return r;
}
__device__ __forceinline__ void upk2(unsigned long long v, float& lo, float& hi) {
    unsigned a, b;
    asm("mov.b64 {%0,%1}, %2;" : "=r"(a), "=r"(b) : "l"(v));
    lo = __uint_as_float(a); hi = __uint_as_float(b);
}
__device__ __forceinline__ unsigned long long bfx2(unsigned u) {
    return pk2(u << 16, u & 0xFFFF0000u);   // bf16x2 -> packed f32x2
}
__device__ __forceinline__ void ffma2(unsigned long long& d,
                                      unsigned long long a,
                                      unsigned long long b) {
    asm("fma.rn.f32x2 %0, %1, %2, %0;" : "+l"(d) : "l"(a), "l"(b));
}

// ---------------------------------------------------------------------------
// Fused transpose + GN partial stats
// ---------------------------------------------------------------------------
__global__ void xpose_gn(const float* __restrict__ x)
{
    __shared__ float t[32][33];
    __shared__ float red[8][4][2];
    const int b = blockIdx.z;
    const int n0 = blockIdx.x * 32, c0 = blockIdx.y * 32;
    const float* xp = x + (size_t)b * CC * NQ;
    const int tx = threadIdx.x, ty = threadIdx.y;

    float vs[4];
    #pragma unroll
    for (int k = 0; k < 4; k++) {
        int cl = k * 8 + ty;
        float v = xp[(size_t)(c0 + cl) * NQ + n0 + tx];
        t[cl][tx] = v;
        vs[k] = v;
    }
    #pragma unroll
    for (int k = 0; k < 4; k++) {
        float s = vs[k], s2 = vs[k] * vs[k];
        #pragma unroll
        for (int o = 16; o; o >>= 1) {
            s  += __shfl_xor_sync(~0u, s,  o);
            s2 += __shfl_xor_sync(~0u, s2, o);
        }
        if (tx == 0) { red[ty][k][0] = s; red[ty][k][1] = s2; }
    }
    __syncthreads();

    __nv_bfloat16* o = g_xt + (size_t)b * NQ * CC;
    #pragma unroll
    for (int k = 0; k < 4; k++) {
        int nl = k * 8 + ty;
        o[(size_t)(n0 + nl) * CC + c0 + tx] = __float2bfloat16_rn(t[tx][nl]);
    }

    if (ty == 0 && tx < 4) {
        float s = 0.f, s2 = 0.f;
        #pragma unroll
        for (int y = 0; y < 8; y++) { s += red[y][tx][0]; s2 += red[y][tx][1]; }
        int grp = blockIdx.y * 4 + tx;
        g_ps [(b * GROUPS + grp) * NTILES + blockIdx.x] = s;
        g_ps2[(b * GROUPS + grp) * NTILES + blockIdx.x] = s2;
    }
}

// ---------------------------------------------------------------------------
// Weight prep with inline GN-stats reduction (gn_finish folded in).
// grid (4, B, 8), block 256.
// ---------------------------------------------------------------------------
__global__ void wprep(const float* __restrict__ wq, const float* __restrict__ bq,
                      const float* __restrict__ wk, const float* __restrict__ bk,
                      const float* __restrict__ wv, const float* __restrict__ bv,
                      const float* __restrict__ wo,
                      const float* __restrict__ gsc, const float* __restrict__ gbi)
{
    const int which = blockIdx.x, b = blockIdx.y;
    const int obase = blockIdx.z * 32;
    const int tid = threadIdx.x;
    const int wid = tid >> 5, lane = tid & 31;

    if (which == 3) {
        #pragma unroll
        for (int oo = 0; oo < 4; oo++) {
            int o = obase + wid + oo * 8;
            #pragma unroll
            for (int cb = 0; cb < CC; cb += 32) {
                int c = cb + lane;
                g_wob[(size_t)o * CC + c] =
                    __float2bfloat16_rn(wo[(size_t)o * CC + c]);
            }
        }
        return;
    }

    const float* W    = which == 0 ? wq : which == 1 ? wk : wv;
    const float* bias = which == 0 ? bq : which == 1 ? bk : bv;

    __shared__ float mean_s[GROUPS], rstd_s[GROUPS];
    __shared__ float coef[CC], sub[CC];

    // inline stats: group g = tid>>3, sub-lane i = tid&7 reduces 16 partials
    {
        int g = tid >> 3, i = tid & 7;
        const float* ps  = g_ps  + (b * GROUPS + g) * NTILES + i * 16;
        const float* ps2 = g_ps2 + (b * GROUPS + g) * NTILES + i * 16;
        float s = 0.f, s2 = 0.f;
        #pragma unroll
        for (int j = 0; j < 16; j++) { s += ps[j]; s2 += ps2[j]; }
        s  += __shfl_xor_sync(~0u, s,  4);
        s2 += __shfl_xor_sync(~0u, s2, 4);
        s  += __shfl_xor_sync(~0u, s,  2);
        s2 += __shfl_xor_sync(~0u, s2, 2);
        s  += __shfl_xor_sync(~0u, s,  1);
        s2 += __shfl_xor_sync(~0u, s2, 1);
        if (i == 0) {
            const float NE = (float)(CPG * NQ);
            float m = s / NE;
            float var = s2 / NE - m * m;
            mean_s[g] = m;
            rstd_s[g] = rsqrtf(var + EPS);
        }
    }
    __syncthreads();
    {
        int c = tid;
        int g = c >> 3;
        float r = rstd_s[g], m = mean_s[g];
        float sc = gsc[c];
        coef[c] = sc * r;
        sub[c]  = gbi[c] - m * r * sc;
    }
    __syncthreads();

    __nv_bfloat16* Wp = g_wpb + (size_t)(b*3 + which) * CC * CC;
    float* bp = g_bp + (b*3 + which) * CC;

    #pragma unroll
    for (int oo = 0; oo < 4; oo++) {
        int o = obase + wid + oo * 8;
        float acc = 0.f;
        #pragma unroll
        for (int cb = 0; cb < CC; cb += 32) {
            int c = cb + lane;
            float w = W[(size_t)o * CC + c];
            Wp[(size_t)o * CC + c] = __float2bfloat16_rn(w * coef[c]);
            acc += w * sub[c];
        }
        #pragma unroll
        for (int off = 16; off; off >>= 1)
            acc += __shfl_xor_sync(~0u, acc, off);
        if (lane == 0) bp[o] = bias[o] + acc;
    }
}

// ---------------------------------------------------------------------------
// Fused QKV GEMM (bf16 MMA, 4-stage cp.async, ONE sync per k-step, 2 CTAs/SM)
// O[b][n][o] = sum_c x^T[n][c] * W'[o][c] + bias'[o]
// Tile 128x128, k-step 32. grid (NQ/128, 6, B).
// ---------------------------------------------------------------------------
#define GEMM_SMEM (4 * 2 * 128 * PADK * 2)   // 4 stages x 2 ops

__global__ void __launch_bounds__(256, 2)
gemm_qkv()
{
    extern __shared__ __nv_bfloat16 smem_bf[];
    __nv_bfloat16* As = smem_bf;                    // [4][128][PADK]
    __nv_bfloat16* Bs = smem_bf + 4*128*PADK;       // [4][128][PADK]
    const unsigned* As32 = (const unsigned*)As;
    const unsigned* Bs32 = (const unsigned*)Bs;

    const int nb    = blockIdx.x * 128;
    const int which = blockIdx.y >> 1;
    const int ob    = (blockIdx.y & 1) * 128;
    const int b     = blockIdx.z;

    const __nv_bfloat16* Xt = g_xt  + (size_t)b * NQ * CC;
    const __nv_bfloat16* W  = g_wpb + (size_t)(b*3 + which) * CC * CC;
    const float* bias = g_bp + (b*3 + which) * CC;

    const int tid  = threadIdx.x;
    const int wid  = tid >> 5, lane = tid & 31;
    const int wm   = wid & 1,  wn   = wid >> 1;
    const int g    = lane >> 2, t   = lane & 3;

    const unsigned as_base = (unsigned)__cvta_generic_to_shared(As);
    const unsigned bs_base = (unsigned)__cvta_generic_to_shared(Bs);

    const int cp_r = tid >> 2, cp_s = tid & 3;

    #define LOAD_STAGE(s, c0)                                                  \
    {                                                                          \
        _Pragma("unroll")                                                      \
        for (int j = 0; j < 2; j++) {                                          \
            int row = cp_r + j * 64;                                           \
            cp16(as_base + (((s)*128 + row) * PADK + cp_s * 8) * 2,            \
                 Xt + (size_t)(nb + row) * CC + (c0) + cp_s * 8);              \
            cp16(bs_base + (((s)*128 + row) * PADK + cp_s * 8) * 2,            \
                 W  + (size_t)(ob + row) * CC + (c0) + cp_s * 8);              \
        }                                                                      \
        CP_COMMIT();                                                           \
    }

    float acc[4][4][4];
    #pragma unroll
    for (int i = 0; i < 4; i++)
        #pragma unroll
        for (int j = 0; j < 4; j++)
            #pragma unroll
            for (int r = 0; r < 4; r++) acc[i][j][r] = 0.f;

    LOAD_STAGE(0, 0);
    LOAD_STAGE(1, 32);
    LOAD_STAGE(2, 64);

    #pragma unroll
    for (int ks = 0; ks < 8; ks++) {
        const int cur = ks & 3;
        if (ks < 6)      { CP_WAIT(2); }
        else if (ks == 6){ CP_WAIT(1); }
        else             { CP_WAIT(0); }
        __syncthreads();
        if (ks < 5) LOAD_STAGE((ks + 3) & 3, (ks + 3) * 32);

        #pragma unroll
        for (int kk = 0; kk < 2; kk++) {
            unsigned afr[4][4], bfr[4][2];
            #pragma unroll
            for (int mt = 0; mt < 4; mt++) {
                int base = (cur*128 + wm*64 + mt*16 + g) * (PADK/2) + kk*8 + t;
                afr[mt][0] = As32[base];
                afr[mt][1] = As32[base + 8*(PADK/2)];
                afr[mt][2] = As32[base + 4];
                afr[mt][3] = As32[base + 8*(PADK/2) + 4];
            }
            #pragma unroll
            for (int nt = 0; nt < 4; nt++) {
                int base = (cur*128 + wn*32 + nt*8 + g) * (PADK/2) + kk*8 + t;
                bfr[nt][0] = Bs32[base];
                bfr[nt][1] = Bs32[base + 4];
            }
            #pragma unroll
            for (int mt = 0; mt < 4; mt++)
                #pragma unroll
                for (int nt = 0; nt < 4; nt++)
                    mma_bf16(acc[mt][nt], afr[mt], bfr[nt]);
        }
    }
    #undef LOAD_STAGE

    __nv_bfloat16* O = (which == 0 ? g_qb : which == 1 ? g_kb : g_vb)
                       + (size_t)b * NQ * CC;
    #pragma unroll
    for (int nt = 0; nt < 4; nt++) {
        int o = ob + wn*32 + nt*8 + 2*t;
        float bb0 = bias[o], bb1 = bias[o + 1];
        #pragma unroll
        for (int mt = 0; mt < 4; mt++) {
            int n0 = nb + wm*64 + mt*16 + g;
            __nv_bfloat162 v0 = {__float2bfloat16_rn(acc[mt][nt][0] + bb0),
                                 __float2bfloat16_rn(acc[mt][nt][1] + bb1)};
            __nv_bfloat162 v1 = {__float2bfloat16_rn(acc[mt][nt][2] + bb0),
                                 __float2bfloat16_rn(acc[mt][nt][3] + bb1)};
            *(__nv_bfloat162*)&O[(size_t)n0 * CC + o]       = v0;
            *(__nv_bfloat162*)&O[(size_t)(n0 + 8) * CC + o] = v1;
        }
    }
}

// ---------------------------------------------------------------------------
// Sparse attention: 128-thread blocks, packed f32x2 FMA
// ---------------------------------------------------------------------------
__global__ void __launch_bounds__(128)
attn_kernel(const int* __restrict__ mask, const int* __restrict__ aidx)
{
    __shared__ int   sidx[4][64];
    __shared__ float sl  [4][64][4];

    const int wrp = threadIdx.x >> 5, l = threadIdx.x & 31;
    const int gw = blockIdx.x * 4 + wrp;
    const int n  = gw & (NQ - 1);
    const int b  = gw >> 12;

    const __nv_bfloat16* qp = g_qb + ((size_t)b * NQ + n) * CC;
    const __nv_bfloat16* Kb = g_kb + (size_t)b * NQ * CC;
    const __nv_bfloat16* Vb = g_vb + (size_t)b * NQ * CC;

    unsigned long long q2[4];
    {
        uint4 qw = *(const uint4*)(qp + 8 * l);
        q2[0] = bfx2(qw.x); q2[1] = bfx2(qw.y);
        q2[2] = bfx2(qw.z); q2[3] = bfx2(qw.w);
    }

    int nact;
    {
        int i0 = aidx[n * KK + l];
        int i1 = aidx[n * KK + l + 32];
        int m0 = mask[n * KK + l];
        int m1 = mask[n * KK + l + 32];
        unsigned bl0 = __ballot_sync(~0u, m0 != 0);
        unsigned bl1 = __ballot_sync(~0u, m1 != 0);
        int cnt0 = __popc(bl0);
        nact = cnt0 + __popc(bl1);
        unsigned below = (1u << l) - 1u;
        if (m0) sidx[wrp][__popc(bl0 & below)]        = i0;
        if (m1) sidx[wrp][cnt0 + __popc(bl1 & below)] = i1;
    }
    __syncwarp();

    const int h = l >> 3, i = l & 7;

    #pragma unroll 4
    for (int key = 0; key < nact; key++) {
        const int idx = sidx[wrp][key];
        uint4 kw = ((const uint4*)(Kb + (size_t)idx * CC))[l];
        unsigned long long a2 = 0ull;
        ffma2(a2, q2[0], bfx2(kw.x));
        ffma2(a2, q2[1], bfx2(kw.y));
        ffma2(a2, q2[2], bfx2(kw.z));
        ffma2(a2, q2[3], bfx2(kw.w));
        float plo, phi; upk2(a2, plo, phi);
        float p = plo + phi;
        p += __shfl_xor_sync(~0u, p, 4);
        p += __shfl_xor_sync(~0u, p, 2);
        p += __shfl_xor_sync(~0u, p, 1);
        if (i == (key & 7)) sl[wrp][key][h] = p;
    }
    __syncwarp();

    float lg[8];
    #pragma unroll
    for (int j = 0; j < 8; j++) {
        int key = i + 8 * j;
        lg[j] = (key < nact) ? sl[wrp][key][h] : -INFINITY;
    }
    float mx = lg[0];
    #pragma unroll
    for (int j = 1; j < 8; j++) mx = fmaxf(mx, lg[j]);
    mx = fmaxf(mx, __shfl_xor_sync(~0u, mx, 4));
    mx = fmaxf(mx, __shfl_xor_sync(~0u, mx, 2));
    mx = fmaxf(mx, __shfl_xor_sync(~0u, mx, 1));

    float e[8], s = 0.f;
    #pragma unroll
    for (int j = 0; j < 8; j++) { e[j] = __expf(lg[j] - mx); s += e[j]; }
    s += __shfl_xor_sync(~0u, s, 4);
    s += __shfl_xor_sync(~0u, s, 2);
    s += __shfl_xor_sync(~0u, s, 1);
    const float inv = 1.f / s;

    #pragma unroll
    for (int j = 0; j < 8; j++)
        sl[wrp][i + 8 * j][h] = e[j] * inv;
    __syncwarp();

    unsigned long long vacc[4] = {0ull, 0ull, 0ull, 0ull};

    #pragma unroll 4
    for (int key = 0; key < nact; key++) {
        const int idx = sidx[wrp][key];
        const float wv = sl[wrp][key][h];
        unsigned wu = __float_as_uint(wv);
        unsigned long long w2 = pk2(wu, wu);
        uint4 vw = ((const uint4*)(Vb + (size_t)idx * CC))[l];
        ffma2(vacc[0], w2, bfx2(vw.x));
        ffma2(vacc[1], w2, bfx2(vw.y));
        ffma2(vacc[2], w2, bfx2(vw.z));
        ffma2(vacc[3], w2, bfx2(vw.w));
    }

    float acc[8];
    upk2(vacc[0], acc[0], acc[1]);
    upk2(vacc[1], acc[2], acc[3]);
    upk2(vacc[2], acc[4], acc[5]);
    upk2(vacc[3], acc[6], acc[7]);

    __nv_bfloat16* at = g_atb + ((size_t)b * NQ + n) * CC;
    #pragma unroll
    for (int j = 0; j < 8; j++) {
        int c = 8 * l + j;                   // c = 64*h + d
        at[(c & 63) * HEADS + h] = __float2bfloat16_rn(acc[j]);
    }
}

// ---------------------------------------------------------------------------
// Output projection + residual (bf16 MMA, 4-stage cp.async, one sync/step)
// ---------------------------------------------------------------------------
__global__ void __launch_bounds__(256, 2)
gemm_out(const float* __restrict__ bo,
         const float* __restrict__ x,  float* __restrict__ out)
{
    extern __shared__ __nv_bfloat16 smem_bf[];
    __nv_bfloat16* As = smem_bf;                    // [4][128][PADK] Wo
    __nv_bfloat16* Bs = smem_bf + 4*128*PADK;       // [4][128][PADK] at
    const unsigned* As32 = (const unsigned*)As;
    const unsigned* Bs32 = (const unsigned*)Bs;

    const int nb = blockIdx.x * 128, ob = blockIdx.y * 128, b = blockIdx.z;
    const __nv_bfloat16* A = g_atb + (size_t)b * NQ * CC;

    const int tid  = threadIdx.x;
    const int wid  = tid >> 5, lane = tid & 31;
    const int wm   = wid & 1,  wn   = wid >> 1;
    const int g    = lane >> 2, t   = lane & 3;

    const unsigned as_base = (unsigned)__cvta_generic_to_shared(As);
    const unsigned bs_base = (unsigned)__cvta_generic_to_shared(Bs);

    const int cp_r = tid >> 2, cp_s = tid & 3;

    #define LOAD_STAGE(s, c0)                                                  \
    {                                                                          \
        _Pragma("unroll")                                                      \
        for (int j = 0; j < 2; j++) {                                          \
            int row = cp_r + j * 64;                                           \
            cp16(as_base + (((s)*128 + row) * PADK + cp_s * 8) * 2,            \
                 g_wob + (size_t)(ob + row) * CC + (c0) + cp_s * 8);           \
            cp16(bs_base + (((s)*128 + row) * PADK + cp_s * 8) * 2,            \
                 A + (size_t)(nb + row) * CC + (c0) + cp_s * 8);               \
        }                                                                      \
        CP_COMMIT();                                                           \
    }

    float acc[4][4][4];
    #pragma unroll
    for (int i = 0; i < 4; i++)
        #pragma unroll
        for (int j = 0; j < 4; j++)
            #pragma unroll
            for (int r = 0; r < 4; r++) acc[i][j][r] = 0.f;

    LOAD_STAGE(0, 0);
    LOAD_STAGE(1, 32);
    LOAD_STAGE(2, 64);

    #pragma unroll
    for (int ks = 0; ks < 8; ks++) {
        const int cur = ks & 3;
        if (ks < 6)      { CP_WAIT(2); }
        else if (ks == 6){ CP_WAIT(1); }
        else             { CP_WAIT(0); }
        __syncthreads();
        if (ks < 5) LOAD_STAGE((ks + 3) & 3, (ks + 3) * 32);

        #pragma unroll
        for (int kk = 0; kk < 2; kk++) {
            unsigned afr[4][4], bfr[4][2];
            #pragma unroll
            for (int mt = 0; mt < 4; mt++) {
                int base = (cur*128 + wm*64 + mt*16 + g) * (PADK/2) + kk*8 + t;
                afr[mt][0] = As32[base];
                afr[mt][1] = As32[base + 8*(PADK/2)];
                afr[mt][2] = As32[base + 4];
                afr[mt][3] = As32[base + 8*(PADK/2) + 4];
            }
            #pragma unroll
            for (int nt = 0; nt < 4; nt++) {
                int base = (cur*128 + wn*32 + nt*8 + g) * (PADK/2) + kk*8 + t;
                bfr[nt][0] = Bs32[base];
                bfr[nt][1] = Bs32[base + 4];
            }
            #pragma unroll
            for (int mt = 0; mt < 4; mt++)
                #pragma unroll
                for (int nt = 0; nt < 4; nt++)
                    mma_bf16(acc[mt][nt], afr[mt], bfr[nt]);
        }
    }
    #undef LOAD_STAGE

    const float* xp = x   + (size_t)b * CC * NQ;
    float*       op = out + (size_t)b * CC * NQ;
    #pragma unroll
    for (int mt = 0; mt < 4; mt++) {
        int o0 = ob + wm*64 + mt*16 + g;
        float bb0 = bo[o0], bb1 = bo[o0 + 8];
        #pragma unroll
        for (int nt = 0; nt < 4; nt++) {
            int n = nb + wn*32 + nt*8 + 2*t;
            size_t base0 = (size_t)o0 * NQ + n;
            size_t base1 = (size_t)(o0 + 8) * NQ + n;
            float2 x0 = *(const float2*)&xp[base0];
            float2 x1 = *(const float2*)&xp[base1];
            float2 v0 = {acc[mt][nt][0] + bb0 + x0.x, acc[mt][nt][1] + bb0 + x0.y};
            float2 v1 = {acc[mt][nt][2] + bb1 + x1.x, acc[mt][nt][3] + bb1 + x1.y};
            *(float2*)&op[base0] = v0;
            *(float2*)&op[base1] = v1;
        }
    }
}

// ---------------------------------------------------------------------------
extern "C" void kernel_launch(void* const* d_in, const int* in_sizes, int n_in,
                              void* d_out, int out_size)
{
    const float* x    = (const float*)d_in[0];
    const int*   mask = (const int*)  d_in[1];
    const int*   aidx = (const int*)  d_in[2];
    const float* gsc  = (const float*)d_in[3];
    const float* gbi  = (const float*)d_in[4];
    const float* wq   = (const float*)d_in[5];
    const float* bq   = (const float*)d_in[6];
    const float* wk   = (const float*)d_in[7];
    const float* bk   = (const float*)d_in[8];
    const float* wv   = (const float*)d_in[9];
    const float* bv   = (const float*)d_in[10];
    const float* wo   = (const float*)d_in[11];
    const float* bo   = (const float*)d_in[12];
    float* out = (float*)d_out;

    cudaFuncSetAttribute(gemm_qkv, cudaFuncAttributeMaxDynamicSharedMemorySize,
                         GEMM_SMEM);
    cudaFuncSetAttribute(gemm_out, cudaFuncAttributeMaxDynamicSharedMemorySize,
                         GEMM_SMEM);

    xpose_gn<<<dim3(NQ / 32, CC / 32, BB), dim3(32, 8)>>>(x);

    wprep<<<dim3(4, BB, 8), 256>>>(wq, bq, wk, bk, wv, bv, wo, gsc, gbi);

    gemm_qkv<<<dim3(NQ / 128, 6, BB), 256, GEMM_SMEM>>>();

    attn_kernel<<<BB * NQ / 4, 128>>>(mask, aidx);

    gemm_out<<<dim3(NQ / 128, CC / 128, BB), 256, GEMM_SMEM>>>(bo, x, out);
}